// round 8
// baseline (speedup 1.0000x reference)
#include <cuda_runtime.h>
#include <math.h>
#include <stdint.h>

#define Bn 131072
#define Dd 256
#define Hh 256
#define Cc 8

// ---------------- scratch (device globals; no allocs allowed) ----------------
__device__ int    g_cnt[Cc];
__device__ int    g_idx[Cc * Bn];
__device__ float  g_h[(size_t)Bn * Hh];          // root hidden copy (gather source)
__device__ float4 g_wfrag[9 * 32768];            // [mat][k8g*32+n8][lane] = {bh0,bh1,bl0,bl1}
__device__ float  g_plog[4][Bn][8];              // partial logits per col-quarter

__global__ void zero_cnt_kernel() {
    if (threadIdx.x < Cc) g_cnt[threadIdx.x] = 0;
}

// ---------------- helpers ----------------
__device__ __forceinline__ void tf32_split(float x, float& hi, float& lo) {
    uint32_t h;
    asm("cvt.rna.tf32.f32 %0, %1;" : "=r"(h) : "f"(x));
    float hf = __uint_as_float(h);
    float r = x - hf;
    uint32_t l;
    asm("cvt.rna.tf32.f32 %0, %1;" : "=r"(l) : "f"(r));
    hi = hf; lo = __uint_as_float(l);
}

__device__ __forceinline__ void mma_tf32(float* d, const uint32_t* a, uint32_t b0, uint32_t b1) {
    asm("mma.sync.aligned.m16n8k8.row.col.f32.tf32.tf32.f32 "
        "{%0,%1,%2,%3}, {%4,%5,%6,%7}, {%8,%9}, {%0,%1,%2,%3};"
        : "+f"(d[0]), "+f"(d[1]), "+f"(d[2]), "+f"(d[3])
        : "r"(a[0]), "r"(a[1]), "r"(a[2]), "r"(a[3]), "r"(b0), "r"(b1));
}

__device__ __forceinline__ uint32_t smem_u32(const void* p) {
    uint32_t a;
    asm("{ .reg .u64 t; cvta.to.shared.u64 t, %1; cvt.u32.u64 %0, t; }" : "=r"(a) : "l"(p));
    return a;
}
#define CP_ASYNC16(dst, src) \
    asm volatile("cp.async.cg.shared.global [%0], [%1], 16;" :: "r"(dst), "l"(src) : "memory")
#define CP_COMMIT()  asm volatile("cp.async.commit_group;" ::: "memory")
#define CP_WAIT0()   asm volatile("cp.async.wait_group 0;" ::: "memory")

// ---------------------------------------------------------------------------
// One-time W fragment split: mat 0 = W1, mats 1..8 = Wc1 experts.
// ---------------------------------------------------------------------------
__global__ __launch_bounds__(256)
void split_wfrag(const float* __restrict__ W1, const float* __restrict__ Wc1) {
    int t = blockIdx.x * 256 + threadIdx.x;       // 9 * 32768 total
    int mat  = t >> 15;
    int r    = t & 32767;
    int lane = r & 31;
    int n8   = (r >> 5) & 31;
    int k8g  = r >> 10;
    const float* W = (mat == 0) ? W1 : (Wc1 + (size_t)(mat - 1) * 65536);
    int k = k8g * 8 + (lane & 3);
    int n = n8 * 8 + (lane >> 2);
    float v0 = W[(size_t)k * 256 + n];
    float v1 = W[(size_t)(k + 4) * 256 + n];
    float h0, l0, h1, l1;
    tf32_split(v0, h0, l0);
    tf32_split(v1, h1, l1);
    g_wfrag[t] = make_float4(h0, h1, l0, l1);
}

// smem (floats): A stages 2x8192 (Ahi 4096 | Alo 4096 each), B stages 2x4096
#define A_STG    8192
#define SM_B0    (2 * A_STG)                  /* 16384 */
#define B_STG    4096
#define SM_FLOATS (2 * A_STG + 2 * B_STG)     /* 24576 */
#define SMEM_BYTES (SM_FLOATS * 4 + 1280)

// ---------------------------------------------------------------------------
// mma.sync 3xTF32 GEMM, BM=256 / BN=128, 512 threads (16 warps: 8m x 2n).
// Out[256 rows, nBase..nBase+128) = relu(A@W + bias). Root fuses partial
// logits into g_plog. B fragments cp.async-staged ONCE per SM per chunk.
// ---------------------------------------------------------------------------
template<bool GATHER>
__global__ __launch_bounds__(512, 1)
void gemm_mma(const float* __restrict__ Ain,
              const float* __restrict__ ball,
              const float* __restrict__ W2,
              float* __restrict__ Out)
{
    extern __shared__ float sm[];
    int* ridx = (int*)(sm + SM_FLOATS);

    const int tid  = threadIdx.x;
    const int wid  = tid >> 5;
    const int lane = tid & 31;
    const int mBase = blockIdx.y * 256;
    const int nBase = blockIdx.x * 128;

    const float* A;
    const float* bias;
    int mat;
    if (GATHER) {
        const int c   = blockIdx.z;
        const int cnt = g_cnt[c];
        if (mBase >= cnt) return;
        A    = g_h;
        bias = ball + c * 256;
        mat  = 1 + c;
        if (tid < 256) {
            int gi = mBase + tid;
            ridx[tid] = (gi < cnt) ? g_idx[c * Bn + gi] : -1;
        }
        __syncthreads();
    } else {
        A    = Ain;
        bias = ball;
        mat  = 0;
    }

    // A staging mapping: thread -> row ar (0..255), k-half ah (8 floats/chunk)
    const int ar = tid >> 1;
    const int ah = tid & 1;
    int grow = GATHER ? ridx[ar] : (mBase + ar);
    const bool aok = (!GATHER) || (grow >= 0);
    const float* ap = A + (size_t)(aok ? grow : 0) * 256 + ah * 8;
    const int ag   = ar & 7;
    const int am16 = ar >> 4;          // 0..15
    const int ahi8 = (ar >> 3) & 1;

    const int bx16 = blockIdx.x * 16;
    const uint32_t smb = smem_u32(sm);

    const int warp_m = wid & 7;        // 8 groups of 32 rows
    const int warp_n = wid >> 3;       // 2 groups of 64 cols

    float acc[2][8][4];
    #pragma unroll
    for (int i = 0; i < 2; i++)
        #pragma unroll
        for (int j = 0; j < 8; j++)
            #pragma unroll
            for (int t = 0; t < 4; t++) acc[i][j][t] = 0.f;

    auto stageA = [&](int buf, const float4* v) {
        float* AHI = sm + buf * A_STG;
        float* ALO = AHI + 4096;
        #pragma unroll
        for (int q = 0; q < 2; q++) {
            int base = ((ah * 16 + am16) * 32 + ag * 4) * 4 + (ahi8 + 2 * q);
            float h0, l0, h1, l1, h2, l2, h3, l3;
            tf32_split(v[q].x, h0, l0);
            tf32_split(v[q].y, h1, l1);
            tf32_split(v[q].z, h2, l2);
            tf32_split(v[q].w, h3, l3);
            AHI[base + 0]  = h0;  ALO[base + 0]  = l0;
            AHI[base + 4]  = h1;  ALO[base + 4]  = l1;
            AHI[base + 8]  = h2;  ALO[base + 8]  = l2;
            AHI[base + 12] = h3;  ALO[base + 12] = l3;
        }
    };
    auto stageB = [&](int buf, int kb) {
        uint32_t dbase = smb + (SM_B0 + buf * B_STG) * 4;
        #pragma unroll
        for (int i = 0; i < 2; i++) {
            int t    = tid + i * 512;
            int ln   = t & 31;
            int n8l  = (t >> 5) & 15;
            int k8l  = t >> 9;
            const float4* src = g_wfrag +
                ((size_t)mat * 1024 + (size_t)(kb * 2 + k8l) * 32 + bx16 + n8l) * 32 + ln;
            CP_ASYNC16(dbase + (uint32_t)t * 16, (const void*)src);
        }
        CP_COMMIT();
    };

    // prologue: chunk 0
    {
        float4 av[2];
        #pragma unroll
        for (int q = 0; q < 2; q++)
            av[q] = aok ? *(const float4*)(ap + q * 4) : make_float4(0.f, 0.f, 0.f, 0.f);
        stageA(0, av);
        stageB(0, 0);
        CP_WAIT0();
        __syncthreads();
    }

    for (int kb = 0; kb < 16; kb++) {
        const int p = kb & 1;
        float4 nv[2];
        if (kb < 15) {
            stageB(p ^ 1, kb + 1);
            #pragma unroll
            for (int q = 0; q < 2; q++)
                nv[q] = aok ? *(const float4*)(ap + (kb + 1) * 16 + q * 4)
                            : make_float4(0.f, 0.f, 0.f, 0.f);
        }

        const float* AHI = sm + p * A_STG;
        const float* ALO = AHI + 4096;
        const float* BST = sm + SM_B0 + p * B_STG;
        #pragma unroll
        for (int k8 = 0; k8 < 2; k8++) {
            uint32_t ahf[2][4], alf[2][4];
            #pragma unroll
            for (int i = 0; i < 2; i++) {
                int m16 = warp_m * 2 + i;
                int off = ((k8 * 16 + m16) * 32 + lane) * 4;
                *(uint4*)ahf[i] = *(const uint4*)(AHI + off);
                *(uint4*)alf[i] = *(const uint4*)(ALO + off);
            }
            #pragma unroll
            for (int jq = 0; jq < 2; jq++) {
                float4 bf[4];
                #pragma unroll
                for (int jj = 0; jj < 4; jj++) {
                    int off = ((k8 * 16 + warp_n * 8 + jq * 4 + jj) * 32 + lane) * 4;
                    bf[jj] = *(const float4*)(BST + off);
                }
                #pragma unroll
                for (int jj = 0; jj < 4; jj++)
                    #pragma unroll
                    for (int i = 0; i < 2; i++)
                        mma_tf32(acc[i][jq * 4 + jj], ahf[i],
                                 __float_as_uint(bf[jj].x), __float_as_uint(bf[jj].y));
                #pragma unroll
                for (int jj = 0; jj < 4; jj++)
                    #pragma unroll
                    for (int i = 0; i < 2; i++)
                        mma_tf32(acc[i][jq * 4 + jj], ahf[i],
                                 __float_as_uint(bf[jj].z), __float_as_uint(bf[jj].w));
                #pragma unroll
                for (int jj = 0; jj < 4; jj++)
                    #pragma unroll
                    for (int i = 0; i < 2; i++)
                        mma_tf32(acc[i][jq * 4 + jj], alf[i],
                                 __float_as_uint(bf[jj].x), __float_as_uint(bf[jj].y));
            }
        }

        if (kb < 15) {
            stageA(p ^ 1, nv);
            CP_WAIT0();
            __syncthreads();
        }
    }

    // ---- root: W2 slice (128 cols x 8 cls) into smem buf0 (dead after chunk 15)
    float* W2s = sm;   // 1024 floats
    if (!GATHER) {
        if (tid < 256) {
            *(float4*)(W2s + tid * 4) = *(const float4*)(W2 + (size_t)nBase * 8 + tid * 4);
        }
        __syncthreads();
    }

    // ---- epilogue: bias + relu, store; root also accumulates partial logits
    const int g  = lane >> 2;
    const int tg = lane & 3;
    float plg[2][2][8];
    if (!GATHER) {
        #pragma unroll
        for (int i = 0; i < 2; i++)
            #pragma unroll
            for (int h = 0; h < 2; h++)
                #pragma unroll
                for (int cls = 0; cls < 8; cls++) plg[i][h][cls] = 0.f;
    }

    #pragma unroll
    for (int i = 0; i < 2; i++) {
        int rl0 = warp_m * 32 + i * 16 + g;
        int rl1 = rl0 + 8;
        int r0, r1;
        if (GATHER) { r0 = ridx[rl0]; r1 = ridx[rl1]; }
        else        { r0 = mBase + rl0; r1 = mBase + rl1; }
        #pragma unroll
        for (int j = 0; j < 8; j++) {
            int colL = warp_n * 64 + j * 8 + tg * 2;
            int col  = nBase + colL;
            float bv0 = __ldg(bias + col);
            float bv1 = __ldg(bias + col + 1);
            float2 v0 = make_float2(fmaxf(acc[i][j][0] + bv0, 0.f),
                                    fmaxf(acc[i][j][1] + bv1, 0.f));
            float2 v1 = make_float2(fmaxf(acc[i][j][2] + bv0, 0.f),
                                    fmaxf(acc[i][j][3] + bv1, 0.f));
            if (!GATHER) {
                *(float2*)(Out + (size_t)r0 * 256 + col) = v0;
                *(float2*)(Out + (size_t)r1 * 256 + col) = v1;
                *(float2*)(g_h + (size_t)r0 * 256 + col) = v0;
                *(float2*)(g_h + (size_t)r1 * 256 + col) = v1;
                const float* w0 = W2s + colL * 8;
                const float* w1 = w0 + 8;
                #pragma unroll
                for (int cls = 0; cls < 8; cls++) {
                    plg[i][0][cls] += v0.x * w0[cls] + v0.y * w1[cls];
                    plg[i][1][cls] += v1.x * w0[cls] + v1.y * w1[cls];
                }
            } else {
                if (r0 >= 0) *(float2*)(Out + (size_t)r0 * 256 + col) = v0;
                if (r1 >= 0) *(float2*)(Out + (size_t)r1 * 256 + col) = v1;
            }
        }
    }

    if (!GATHER) {
        #pragma unroll
        for (int i = 0; i < 2; i++)
            #pragma unroll
            for (int h = 0; h < 2; h++)
                #pragma unroll
                for (int cls = 0; cls < 8; cls++) {
                    float v = plg[i][h][cls];
                    v += __shfl_xor_sync(0xffffffffu, v, 1);
                    v += __shfl_xor_sync(0xffffffffu, v, 2);
                    plg[i][h][cls] = v;
                }
        if (tg == 0) {
            int q = blockIdx.x * 2 + warp_n;
            #pragma unroll
            for (int i = 0; i < 2; i++) {
                int r0 = mBase + warp_m * 32 + i * 16 + g;
                float* p0 = &g_plog[q][r0][0];
                *(float4*)(p0)     = *(float4*)&plg[i][0][0];
                *(float4*)(p0 + 4) = *(float4*)&plg[i][0][4];
                float* p1 = &g_plog[q][r0 + 8][0];
                *(float4*)(p1)     = *(float4*)&plg[i][1][0];
                *(float4*)(p1 + 4) = *(float4*)&plg[i][1][4];
            }
        }
    }
}

// ---------------------------------------------------------------------------
// Routing: sum 4 partial-logit quarters, softmax, tau-mask argmax, compact.
// ---------------------------------------------------------------------------
__global__ __launch_bounds__(256)
void route_kernel(const float* __restrict__ b2, const float* __restrict__ tau,
                  float* __restrict__ outLogits, float* __restrict__ outDepth)
{
    const int s = blockIdx.x * 256 + threadIdx.x;
    float lg[8];
    #pragma unroll
    for (int j = 0; j < 8; j++) lg[j] = __ldg(b2 + j);
    #pragma unroll
    for (int q = 0; q < 4; q++) {
        float4 p0 = *(const float4*)&g_plog[q][s][0];
        float4 p1 = *(const float4*)&g_plog[q][s][4];
        lg[0] += p0.x; lg[1] += p0.y; lg[2] += p0.z; lg[3] += p0.w;
        lg[4] += p1.x; lg[5] += p1.y; lg[6] += p1.z; lg[7] += p1.w;
    }
    float mx = -1e30f;
    #pragma unroll
    for (int j = 0; j < 8; j++) mx = fmaxf(mx, lg[j]);
    float e[8], ss = 0.f;
    #pragma unroll
    for (int j = 0; j < 8; j++) { e[j] = expf(lg[j] - mx); ss += e[j]; }
    float inv = 1.0f / ss;
    int best = -1; float bp = -1.f;
    #pragma unroll
    for (int j = 0; j < 8; j++) {
        float pj = e[j] * inv;
        if (pj >= __ldg(tau + j) && pj > bp) { bp = pj; best = j; }
    }
    float* lo = outLogits + (size_t)s * 8;
    *(float4*)(lo)     = make_float4(lg[0], lg[1], lg[2], lg[3]);
    *(float4*)(lo + 4) = make_float4(lg[4], lg[5], lg[6], lg[7]);
    outDepth[s] = (best >= 0) ? 1.0f : 0.0f;
    if (best >= 0) {
        int pos = atomicAdd(&g_cnt[best], 1);
        g_idx[best * Bn + pos] = s;
    }
}

// ---------------------------------------------------------------------------
// Expert head over compacted lists.
// ---------------------------------------------------------------------------
__global__ __launch_bounds__(256)
void expert_head(const float* __restrict__ Hbuf,
                 const float* __restrict__ Wc2, const float* __restrict__ bc2,
                 float* __restrict__ outLogits)
{
    const int c    = blockIdx.z;
    const int cnt  = g_cnt[c];
    const int base = blockIdx.y * 128;
    if (base >= cnt) return;

    __shared__ float Wst[8][256];
    __shared__ float bcs[8];
    const int tid = threadIdx.x;
    const float* W = Wc2 + (size_t)c * 2048;
    for (int i = tid; i < 2048; i += 256) Wst[i & 7][i >> 3] = W[i];
    if (tid < 8) bcs[tid] = bc2[c * 8 + tid];
    __syncthreads();

    const int wid = tid >> 5, lane = tid & 31;

    for (int grp = 0; grp < 4; grp++) {
        const int gib = base + wid * 16 + grp * 4;
        int s_0 = (gib + 0 < cnt) ? g_idx[c * Bn + gib + 0] : -1;
        int s_1 = (gib + 1 < cnt) ? g_idx[c * Bn + gib + 1] : -1;
        int s_2 = (gib + 2 < cnt) ? g_idx[c * Bn + gib + 2] : -1;
        int s_3 = (gib + 3 < cnt) ? g_idx[c * Bn + gib + 3] : -1;
        if (s_0 < 0) continue;

        float a0[8], a1[8], a2[8], a3[8];
        #pragma unroll
        for (int j = 0; j < 8; j++) a0[j] = a1[j] = a2[j] = a3[j] = 0.f;
        #pragma unroll
        for (int t = 0; t < 8; t++) {
            int col = t * 32 + lane;
            float w[8];
            #pragma unroll
            for (int j = 0; j < 8; j++) w[j] = Wst[j][col];
            float h0 = Hbuf[(size_t)s_0 * 256 + col];
            float h1 = (s_1 >= 0) ? Hbuf[(size_t)s_1 * 256 + col] : 0.f;
            float h2 = (s_2 >= 0) ? Hbuf[(size_t)s_2 * 256 + col] : 0.f;
            float h3 = (s_3 >= 0) ? Hbuf[(size_t)s_3 * 256 + col] : 0.f;
            #pragma unroll
            for (int j = 0; j < 8; j++) {
                a0[j] += h0 * w[j]; a1[j] += h1 * w[j];
                a2[j] += h2 * w[j]; a3[j] += h3 * w[j];
            }
        }
        #pragma unroll
        for (int j = 0; j < 8; j++) {
            #pragma unroll
            for (int off = 16; off; off >>= 1) {
                a0[j] += __shfl_xor_sync(0xffffffffu, a0[j], off);
                a1[j] += __shfl_xor_sync(0xffffffffu, a1[j], off);
                a2[j] += __shfl_xor_sync(0xffffffffu, a2[j], off);
                a3[j] += __shfl_xor_sync(0xffffffffu, a3[j], off);
            }
        }
        if (lane < 4) {
            int s = (lane == 0) ? s_0 : (lane == 1) ? s_1 : (lane == 2) ? s_2 : s_3;
            if (s >= 0) {
                float* lo = outLogits + (size_t)s * 8;
                #pragma unroll
                for (int j = 0; j < 8; j++) {
                    float v = (lane == 0) ? a0[j] : (lane == 1) ? a1[j] : (lane == 2) ? a2[j] : a3[j];
                    lo[j] = v + bcs[j];
                }
            }
        }
    }
}

// ---------------------------------------------------------------------------
extern "C" void kernel_launch(void* const* d_in, const int* in_sizes, int n_in,
                              void* d_out, int out_size)
{
    const float* x   = (const float*)d_in[0];
    const float* W1  = (const float*)d_in[1];
    const float* b1  = (const float*)d_in[2];
    const float* W2  = (const float*)d_in[3];
    const float* b2  = (const float*)d_in[4];
    const float* Wc1 = (const float*)d_in[5];
    const float* bc1 = (const float*)d_in[6];
    const float* Wc2 = (const float*)d_in[7];
    const float* bc2 = (const float*)d_in[8];
    const float* tau = (const float*)d_in[9];

    float* out       = (float*)d_out;
    float* outLogits = out;
    float* outH      = out + (size_t)Bn * Cc;
    float* outDepth  = out + (size_t)Bn * (Cc + Hh);

    static bool attr_done = false;
    if (!attr_done) {
        cudaFuncSetAttribute(gemm_mma<false>, cudaFuncAttributeMaxDynamicSharedMemorySize, SMEM_BYTES);
        cudaFuncSetAttribute(gemm_mma<true>,  cudaFuncAttributeMaxDynamicSharedMemorySize, SMEM_BYTES);
        attr_done = true;
    }

    zero_cnt_kernel<<<1, 32>>>();

    // One-time W fragment split (W1 + 8 experts)
    split_wfrag<<<(9 * 32768) / 256, 256>>>(W1, Wc1);

    // Root: h = relu(x @ W1 + b1) -> outH + g_h, fused partial logits -> g_plog
    gemm_mma<false><<<dim3(2, Bn / 256, 1), 512, SMEM_BYTES>>>(x, b1, W2, outH);

    // Routing from partial logits
    route_kernel<<<Bn / 256, 256>>>(b2, tau, outLogits, outDepth);

    // Expert dense: gather from g_h, write routed rows of outH
    gemm_mma<true><<<dim3(2, Bn / 256, Cc), 512, SMEM_BYTES>>>(nullptr, bc1, nullptr, outH);

    // Expert head: overwrite logits for routed rows
    expert_head<<<dim3(1, Bn / 128, Cc), 256>>>(outH, Wc2, bc2, outLogits);
}

// round 11
// speedup vs baseline: 1.7483x; 1.7483x over previous
#include <cuda_runtime.h>
#include <cuda_fp16.h>
#include <math.h>
#include <stdint.h>

#define Bn 131072
#define Dd 256
#define Hh 256
#define Cc 8

// ---------------- scratch (device globals; no allocs allowed) ----------------
__device__ int    g_cnt[Cc];
__device__ int    g_idx[Cc * Bn];
__device__ float  g_h[(size_t)Bn * Hh];          // root hidden copy (gather source)
__device__ uint4  g_wfrag[9 * 16 * 32 * 32];     // [mat][kc][n8][lane] = {b0hi,b1hi,b0lo,b1lo}
__device__ float  g_plog[4][Bn][8];              // partial logits per col-quarter

__global__ void zero_cnt_kernel() {
    if (threadIdx.x < Cc) g_cnt[threadIdx.x] = 0;
}

// ---------------- helpers ----------------
__device__ __forceinline__ uint32_t pack_h2(float x, float y) {
    __half2 h = __floats2half2_rn(x, y);
    return *(uint32_t*)&h;
}
__device__ __forceinline__ void h_split(float x, float& hi, float& lo) {
    __half h = __float2half_rn(x);
    hi = __half2float(h);
    lo = x - hi;
}

__device__ __forceinline__ void mma_f16(float* d, const uint32_t* a, uint32_t b0, uint32_t b1) {
    asm("mma.sync.aligned.m16n8k16.row.col.f32.f16.f16.f32 "
        "{%0,%1,%2,%3}, {%4,%5,%6,%7}, {%8,%9}, {%0,%1,%2,%3};"
        : "+f"(d[0]), "+f"(d[1]), "+f"(d[2]), "+f"(d[3])
        : "r"(a[0]), "r"(a[1]), "r"(a[2]), "r"(a[3]), "r"(b0), "r"(b1));
}
__device__ __forceinline__ void ldmatrix_x4(uint32_t* r, uint32_t addr) {
    asm volatile("ldmatrix.sync.aligned.m8n8.x4.shared.b16 {%0,%1,%2,%3}, [%4];"
        : "=r"(r[0]), "=r"(r[1]), "=r"(r[2]), "=r"(r[3]) : "r"(addr));
}
__device__ __forceinline__ uint32_t smem_u32(const void* p) {
    uint32_t a;
    asm("{ .reg .u64 t; cvta.to.shared.u64 t, %1; cvt.u32.u64 %0, t; }" : "=r"(a) : "l"(p));
    return a;
}
#define CP_ASYNC16(dst, src) \
    asm volatile("cp.async.cg.shared.global [%0], [%1], 16;" :: "r"(dst), "l"(src) : "memory")
#define CP_COMMIT()  asm volatile("cp.async.commit_group;" ::: "memory")
#define CP_WAIT0()   asm volatile("cp.async.wait_group 0;" ::: "memory")

// ---------------------------------------------------------------------------
// One-time W fragment split (fp16 hi/lo) in m16n8k16 B-fragment order.
// b0: k = kc*16 + (lane%4)*2 + {0,1}; b1: k+8; n = n8*8 + lane/4.
// ---------------------------------------------------------------------------
__global__ __launch_bounds__(256)
void split_wfrag(const float* __restrict__ W1, const float* __restrict__ Wc1) {
    int t = blockIdx.x * 256 + threadIdx.x;       // 9*16*32*32 = 147456 total
    int lane = t & 31;
    int n8   = (t >> 5) & 31;
    int kc   = (t >> 10) & 15;
    int mat  = t >> 14;
    const float* W = (mat == 0) ? W1 : (Wc1 + (size_t)(mat - 1) * 65536);
    int k = kc * 16 + (lane & 3) * 2;
    int n = n8 * 8 + (lane >> 2);
    float v00 = W[(size_t)k * 256 + n];
    float v01 = W[(size_t)(k + 1) * 256 + n];
    float v10 = W[(size_t)(k + 8) * 256 + n];
    float v11 = W[(size_t)(k + 9) * 256 + n];
    float h00, l00, h01, l01, h10, l10, h11, l11;
    h_split(v00, h00, l00);
    h_split(v01, h01, l01);
    h_split(v10, h10, l10);
    h_split(v11, h11, l11);
    uint4 f;
    f.x = pack_h2(h00, h01);   // b0hi
    f.y = pack_h2(h10, h11);   // b1hi
    f.z = pack_h2(l00, l01);   // b0lo
    f.w = pack_h2(l10, l11);   // b1lo
    g_wfrag[t] = f;
}

// smem layout (bytes): A stages 2 x (hi 4KB | lo 4KB) = 16KB, B stages 2 x 8KB
#define SM_A(s)   ((s) * 8192)
#define SM_ALO_OFF 4096
#define SM_B(s)   (16384 + (s) * 8192)
#define SM_BYTES_MAIN 32768
#define SMEM_BYTES (SM_BYTES_MAIN + 1536)

// A smem addressing: row r (0..127), kblock c (0/1, 16B each), xor swizzle
__device__ __forceinline__ int a_off(int r, int c) {
    return r * 32 + ((c ^ ((r >> 2) & 1)) << 4);
}

// ---------------------------------------------------------------------------
// fp16 2-split (3-term) GEMM: Out[128 rows, nBase..+128) = relu(A@W + bias)
// KC=16 (one m16n8k16 step per chunk). Root fuses partial logits.
// ---------------------------------------------------------------------------
template<bool GATHER>
__global__ __launch_bounds__(256, 2)
void gemm_mma(const float* __restrict__ Ain,
              const float* __restrict__ ball,
              const float* __restrict__ W2,
              float* __restrict__ Out)
{
    extern __shared__ char sm[];
    int* ridx = (int*)(sm + SM_BYTES_MAIN);
    float* W2s = (float*)(sm);   // reused after mainloop (root only)

    const int tid  = threadIdx.x;
    const int wid  = tid >> 5;
    const int lane = tid & 31;
    const int mBase = blockIdx.y * 128;
    const int nBase = blockIdx.x * 128;

    const float* A;
    const float* bias;
    int mat;
    if (GATHER) {
        const int c   = blockIdx.z;
        const int cnt = g_cnt[c];
        if (mBase >= cnt) return;
        A    = g_h;
        bias = ball + c * 256;
        mat  = 1 + c;
        if (tid < 128) {
            int gi = mBase + tid;
            ridx[tid] = (gi < cnt) ? g_idx[c * Bn + gi] : -1;
        }
        __syncthreads();
    } else {
        A    = Ain;
        bias = ball;
        mat  = 0;
    }

    // A staging mapping: thread -> row ar (0..127), k-half ah (8 floats/chunk)
    const int ar = tid >> 1;
    const int ah = tid & 1;
    int grow = GATHER ? ridx[ar] : (mBase + ar);
    const bool aok = (!GATHER) || (grow >= 0);
    const float* ap = A + (size_t)(aok ? grow : 0) * 256 + ah * 8;
    const int aoff = a_off(ar, ah);

    const int bx16 = blockIdx.x * 16;
    const uint32_t smb = smem_u32(sm);

    const int warp_m = wid & 3;    // 4 groups of 32 rows
    const int warp_n = wid >> 2;   // 2 groups of 64 cols

    // ldmatrix per-lane byte offsets for the 2 m16 tiles of this warp
    int lm_off[2];
    {
        int mt = lane >> 3;
        int kb2 = mt >> 1;
        #pragma unroll
        for (int i = 0; i < 2; i++) {
            int row = warp_m * 32 + i * 16 + (mt & 1) * 8 + (lane & 7);
            lm_off[i] = a_off(row, kb2);
        }
    }

    float acc[2][8][4];
    #pragma unroll
    for (int i = 0; i < 2; i++)
        #pragma unroll
        for (int j = 0; j < 8; j++)
            #pragma unroll
            for (int t = 0; t < 4; t++) acc[i][j][t] = 0.f;

    auto stageA = [&](int buf, const float4* v) {
        // 8 floats -> 4 hi pairs + 4 lo pairs -> two STS.128
        uint4 hi4, lo4;
        float h0, l0, h1, l1;
        h_split(v[0].x, h0, l0); h_split(v[0].y, h1, l1);
        hi4.x = pack_h2(h0, h1); lo4.x = pack_h2(l0, l1);
        h_split(v[0].z, h0, l0); h_split(v[0].w, h1, l1);
        hi4.y = pack_h2(h0, h1); lo4.y = pack_h2(l0, l1);
        h_split(v[1].x, h0, l0); h_split(v[1].y, h1, l1);
        hi4.z = pack_h2(h0, h1); lo4.z = pack_h2(l0, l1);
        h_split(v[1].z, h0, l0); h_split(v[1].w, h1, l1);
        hi4.w = pack_h2(h0, h1); lo4.w = pack_h2(l0, l1);
        *(uint4*)(sm + SM_A(buf) + aoff)              = hi4;
        *(uint4*)(sm + SM_A(buf) + SM_ALO_OFF + aoff) = lo4;
    };
    auto stageB = [&](int buf, int kb) {
        uint32_t dbase = smb + SM_B(buf);
        #pragma unroll
        for (int i = 0; i < 2; i++) {
            int t   = tid + i * 256;               // 0..511
            int ln  = t & 31;
            int n8l = t >> 5;                      // 0..15
            const uint4* src = g_wfrag +
                ((size_t)(mat * 16 + kb) * 32 + bx16 + n8l) * 32 + ln;
            CP_ASYNC16(dbase + (uint32_t)t * 16, (const void*)src);
        }
        CP_COMMIT();
    };

    // prologue: chunk 0
    {
        float4 av[2];
        av[0] = aok ? *(const float4*)(ap)     : make_float4(0.f, 0.f, 0.f, 0.f);
        av[1] = aok ? *(const float4*)(ap + 4) : make_float4(0.f, 0.f, 0.f, 0.f);
        stageA(0, av);
        stageB(0, 0);
        CP_WAIT0();
        __syncthreads();
    }

    for (int kb = 0; kb < 16; kb++) {
        const int p = kb & 1;
        float4 nv[2];
        if (kb < 15) {
            stageB(p ^ 1, kb + 1);
            nv[0] = aok ? *(const float4*)(ap + (kb + 1) * 16)     : make_float4(0.f, 0.f, 0.f, 0.f);
            nv[1] = aok ? *(const float4*)(ap + (kb + 1) * 16 + 4) : make_float4(0.f, 0.f, 0.f, 0.f);
        }

        // A fragments via ldmatrix
        uint32_t ahf[2][4], alf[2][4];
        #pragma unroll
        for (int i = 0; i < 2; i++) {
            ldmatrix_x4(ahf[i], smb + SM_A(p) + lm_off[i]);
            ldmatrix_x4(alf[i], smb + SM_A(p) + SM_ALO_OFF + lm_off[i]);
        }

        const char* BST = sm + SM_B(p);
        #pragma unroll
        for (int j = 0; j < 8; j++) {
            uint4 bf = *(const uint4*)(BST + (((warp_n * 8 + j) * 32 + lane) << 4));
            #pragma unroll
            for (int i = 0; i < 2; i++) {
                mma_f16(acc[i][j], ahf[i], bf.x, bf.y);   // hi*hi
                mma_f16(acc[i][j], ahf[i], bf.z, bf.w);   // hi*lo
                mma_f16(acc[i][j], alf[i], bf.x, bf.y);   // lo*hi
            }
        }

        if (kb < 15) {
            stageA(p ^ 1, nv);
            CP_WAIT0();
            __syncthreads();
        }
    }

    // ---- root: W2 slice (128 cols x 8 cls) into smem (dead after mainloop)
    if (!GATHER) {
        __syncthreads();
        if (tid < 256) {
            *(float4*)(W2s + tid * 4) = *(const float4*)(W2 + (size_t)nBase * 8 + tid * 4);
        }
        __syncthreads();
    }

    // ---- epilogue: bias + relu, store; root also accumulates partial logits
    const int g  = lane >> 2;
    const int tg = lane & 3;
    float plg[2][2][8];
    if (!GATHER) {
        #pragma unroll
        for (int i = 0; i < 2; i++)
            #pragma unroll
            for (int h = 0; h < 2; h++)
                #pragma unroll
                for (int cls = 0; cls < 8; cls++) plg[i][h][cls] = 0.f;
    }

    #pragma unroll
    for (int i = 0; i < 2; i++) {
        int rl0 = warp_m * 32 + i * 16 + g;
        int rl1 = rl0 + 8;
        int r0, r1;
        if (GATHER) { r0 = ridx[rl0]; r1 = ridx[rl1]; }
        else        { r0 = mBase + rl0; r1 = mBase + rl1; }
        #pragma unroll
        for (int j = 0; j < 8; j++) {
            int colL = warp_n * 64 + j * 8 + tg * 2;
            int col  = nBase + colL;
            float bv0 = __ldg(bias + col);
            float bv1 = __ldg(bias + col + 1);
            float2 v0 = make_float2(fmaxf(acc[i][j][0] + bv0, 0.f),
                                    fmaxf(acc[i][j][1] + bv1, 0.f));
            float2 v1 = make_float2(fmaxf(acc[i][j][2] + bv0, 0.f),
                                    fmaxf(acc[i][j][3] + bv1, 0.f));
            if (!GATHER) {
                *(float2*)(Out + (size_t)r0 * 256 + col) = v0;
                *(float2*)(Out + (size_t)r1 * 256 + col) = v1;
                *(float2*)(g_h + (size_t)r0 * 256 + col) = v0;
                *(float2*)(g_h + (size_t)r1 * 256 + col) = v1;
                const float* w0 = W2s + colL * 8;
                const float* w1 = w0 + 8;
                #pragma unroll
                for (int cls = 0; cls < 8; cls++) {
                    plg[i][0][cls] += v0.x * w0[cls] + v0.y * w1[cls];
                    plg[i][1][cls] += v1.x * w0[cls] + v1.y * w1[cls];
                }
            } else {
                if (r0 >= 0) *(float2*)(Out + (size_t)r0 * 256 + col) = v0;
                if (r1 >= 0) *(float2*)(Out + (size_t)r1 * 256 + col) = v1;
            }
        }
    }

    if (!GATHER) {
        #pragma unroll
        for (int i = 0; i < 2; i++)
            #pragma unroll
            for (int h = 0; h < 2; h++)
                #pragma unroll
                for (int cls = 0; cls < 8; cls++) {
                    float v = plg[i][h][cls];
                    v += __shfl_xor_sync(0xffffffffu, v, 1);
                    v += __shfl_xor_sync(0xffffffffu, v, 2);
                    plg[i][h][cls] = v;
                }
        if (tg == 0) {
            int q = blockIdx.x * 2 + warp_n;
            #pragma unroll
            for (int i = 0; i < 2; i++) {
                int r0 = mBase + warp_m * 32 + i * 16 + g;
                float* p0 = &g_plog[q][r0][0];
                *(float4*)(p0)     = *(float4*)&plg[i][0][0];
                *(float4*)(p0 + 4) = *(float4*)&plg[i][0][4];
                float* p1 = &g_plog[q][r0 + 8][0];
                *(float4*)(p1)     = *(float4*)&plg[i][1][0];
                *(float4*)(p1 + 4) = *(float4*)&plg[i][1][4];
            }
        }
    }
}

// ---------------------------------------------------------------------------
// Routing: sum 4 partial-logit quarters, softmax, tau-mask argmax, compact.
// ---------------------------------------------------------------------------
__global__ __launch_bounds__(256)
void route_kernel(const float* __restrict__ b2, const float* __restrict__ tau,
                  float* __restrict__ outLogits, float* __restrict__ outDepth)
{
    const int s = blockIdx.x * 256 + threadIdx.x;
    float lg[8];
    #pragma unroll
    for (int j = 0; j < 8; j++) lg[j] = __ldg(b2 + j);
    #pragma unroll
    for (int q = 0; q < 4; q++) {
        float4 p0 = *(const float4*)&g_plog[q][s][0];
        float4 p1 = *(const float4*)&g_plog[q][s][4];
        lg[0] += p0.x; lg[1] += p0.y; lg[2] += p0.z; lg[3] += p0.w;
        lg[4] += p1.x; lg[5] += p1.y; lg[6] += p1.z; lg[7] += p1.w;
    }
    float mx = -1e30f;
    #pragma unroll
    for (int j = 0; j < 8; j++) mx = fmaxf(mx, lg[j]);
    float e[8], ss = 0.f;
    #pragma unroll
    for (int j = 0; j < 8; j++) { e[j] = expf(lg[j] - mx); ss += e[j]; }
    float inv = 1.0f / ss;
    int best = -1; float bp = -1.f;
    #pragma unroll
    for (int j = 0; j < 8; j++) {
        float pj = e[j] * inv;
        if (pj >= __ldg(tau + j) && pj > bp) { bp = pj; best = j; }
    }
    float* lo = outLogits + (size_t)s * 8;
    *(float4*)(lo)     = make_float4(lg[0], lg[1], lg[2], lg[3]);
    *(float4*)(lo + 4) = make_float4(lg[4], lg[5], lg[6], lg[7]);
    outDepth[s] = (best >= 0) ? 1.0f : 0.0f;
    if (best >= 0) {
        int pos = atomicAdd(&g_cnt[best], 1);
        g_idx[best * Bn + pos] = s;
    }
}

// ---------------------------------------------------------------------------
// Expert head over compacted lists.
// ---------------------------------------------------------------------------
__global__ __launch_bounds__(256)
void expert_head(const float* __restrict__ Hbuf,
                 const float* __restrict__ Wc2, const float* __restrict__ bc2,
                 float* __restrict__ outLogits)
{
    const int c    = blockIdx.z;
    const int cnt  = g_cnt[c];
    const int base = blockIdx.y * 128;
    if (base >= cnt) return;

    __shared__ float Wst[8][256];
    __shared__ float bcs[8];
    const int tid = threadIdx.x;
    const float* W = Wc2 + (size_t)c * 2048;
    for (int i = tid; i < 2048; i += 256) Wst[i & 7][i >> 3] = W[i];
    if (tid < 8) bcs[tid] = bc2[c * 8 + tid];
    __syncthreads();

    const int wid = tid >> 5, lane = tid & 31;

    for (int grp = 0; grp < 4; grp++) {
        const int gib = base + wid * 16 + grp * 4;
        int s_0 = (gib + 0 < cnt) ? g_idx[c * Bn + gib + 0] : -1;
        int s_1 = (gib + 1 < cnt) ? g_idx[c * Bn + gib + 1] : -1;
        int s_2 = (gib + 2 < cnt) ? g_idx[c * Bn + gib + 2] : -1;
        int s_3 = (gib + 3 < cnt) ? g_idx[c * Bn + gib + 3] : -1;
        if (s_0 < 0) continue;

        float a0[8], a1[8], a2[8], a3[8];
        #pragma unroll
        for (int j = 0; j < 8; j++) a0[j] = a1[j] = a2[j] = a3[j] = 0.f;
        #pragma unroll
        for (int t = 0; t < 8; t++) {
            int col = t * 32 + lane;
            float w[8];
            #pragma unroll
            for (int j = 0; j < 8; j++) w[j] = Wst[j][col];
            float h0 = Hbuf[(size_t)s_0 * 256 + col];
            float h1 = (s_1 >= 0) ? Hbuf[(size_t)s_1 * 256 + col] : 0.f;
            float h2 = (s_2 >= 0) ? Hbuf[(size_t)s_2 * 256 + col] : 0.f;
            float h3 = (s_3 >= 0) ? Hbuf[(size_t)s_3 * 256 + col] : 0.f;
            #pragma unroll
            for (int j = 0; j < 8; j++) {
                a0[j] += h0 * w[j]; a1[j] += h1 * w[j];
                a2[j] += h2 * w[j]; a3[j] += h3 * w[j];
            }
        }
        #pragma unroll
        for (int j = 0; j < 8; j++) {
            #pragma unroll
            for (int off = 16; off; off >>= 1) {
                a0[j] += __shfl_xor_sync(0xffffffffu, a0[j], off);
                a1[j] += __shfl_xor_sync(0xffffffffu, a1[j], off);
                a2[j] += __shfl_xor_sync(0xffffffffu, a2[j], off);
                a3[j] += __shfl_xor_sync(0xffffffffu, a3[j], off);
            }
        }
        if (lane < 4) {
            int s = (lane == 0) ? s_0 : (lane == 1) ? s_1 : (lane == 2) ? s_2 : s_3;
            if (s >= 0) {
                float* lo = outLogits + (size_t)s * 8;
                #pragma unroll
                for (int j = 0; j < 8; j++) {
                    float v = (lane == 0) ? a0[j] : (lane == 1) ? a1[j] : (lane == 2) ? a2[j] : a3[j];
                    lo[j] = v + bcs[j];
                }
            }
        }
    }
}

// ---------------------------------------------------------------------------
extern "C" void kernel_launch(void* const* d_in, const int* in_sizes, int n_in,
                              void* d_out, int out_size)
{
    const float* x   = (const float*)d_in[0];
    const float* W1  = (const float*)d_in[1];
    const float* b1  = (const float*)d_in[2];
    const float* W2  = (const float*)d_in[3];
    const float* b2  = (const float*)d_in[4];
    const float* Wc1 = (const float*)d_in[5];
    const float* bc1 = (const float*)d_in[6];
    const float* Wc2 = (const float*)d_in[7];
    const float* bc2 = (const float*)d_in[8];
    const float* tau = (const float*)d_in[9];

    float* out       = (float*)d_out;
    float* outLogits = out;
    float* outH      = out + (size_t)Bn * Cc;
    float* outDepth  = out + (size_t)Bn * (Cc + Hh);

    static bool attr_done = false;
    if (!attr_done) {
        cudaFuncSetAttribute(gemm_mma<false>, cudaFuncAttributeMaxDynamicSharedMemorySize, SMEM_BYTES);
        cudaFuncSetAttribute(gemm_mma<true>,  cudaFuncAttributeMaxDynamicSharedMemorySize, SMEM_BYTES);
        attr_done = true;
    }

    zero_cnt_kernel<<<1, 32>>>();

    // One-time W fragment split (W1 + 8 experts)
    split_wfrag<<<(9 * 16 * 32 * 32) / 256, 256>>>(W1, Wc1);

    // Root: h = relu(x @ W1 + b1) -> outH + g_h, fused partial logits -> g_plog
    gemm_mma<false><<<dim3(2, Bn / 128, 1), 256, SMEM_BYTES>>>(x, b1, W2, outH);

    // Routing from partial logits
    route_kernel<<<Bn / 256, 256>>>(b2, tau, outLogits, outDepth);

    // Expert dense: gather from g_h, write routed rows of outH
    gemm_mma<true><<<dim3(2, Bn / 128, Cc), 256, SMEM_BYTES>>>(nullptr, bc1, nullptr, outH);

    // Expert head: overwrite logits for routed rows
    expert_head<<<dim3(1, Bn / 128, Cc), 256>>>(outH, Wc2, bc2, outLogits);
}

// round 14
// speedup vs baseline: 1.7905x; 1.0242x over previous
#include <cuda_runtime.h>
#include <cuda_fp16.h>
#include <math.h>
#include <stdint.h>

#define Bn 131072
#define Dd 256
#define Hh 256
#define Cc 8

// ---------------- scratch (device globals; no allocs allowed) ----------------
__device__ int    g_cnt[Cc];
__device__ int    g_idx[Cc * Bn];
__device__ float  g_h[(size_t)Bn * Hh];          // root hidden copy (gather source)
__device__ uint4  g_wfrag[9 * 16 * 32 * 32];     // [mat][kc][n8][lane] = {b0hi,b1hi,b0lo,b1lo}
__device__ float  g_plog[4][Bn][8];              // partial logits per col-quarter (reused by experts)

__global__ void zero_cnt_kernel() {
    if (threadIdx.x < Cc) g_cnt[threadIdx.x] = 0;
}

// ---------------- helpers ----------------
__device__ __forceinline__ uint32_t pack_h2(float x, float y) {
    __half2 h = __floats2half2_rn(x, y);
    return *(uint32_t*)&h;
}
__device__ __forceinline__ void h_split(float x, float& hi, float& lo) {
    __half h = __float2half_rn(x);
    hi = __half2float(h);
    lo = x - hi;
}

__device__ __forceinline__ void mma_f16(float* d, const uint32_t* a, uint32_t b0, uint32_t b1) {
    asm("mma.sync.aligned.m16n8k16.row.col.f32.f16.f16.f32 "
        "{%0,%1,%2,%3}, {%4,%5,%6,%7}, {%8,%9}, {%0,%1,%2,%3};"
        : "+f"(d[0]), "+f"(d[1]), "+f"(d[2]), "+f"(d[3])
        : "r"(a[0]), "r"(a[1]), "r"(a[2]), "r"(a[3]), "r"(b0), "r"(b1));
}
__device__ __forceinline__ void ldmatrix_x4(uint32_t* r, uint32_t addr) {
    asm volatile("ldmatrix.sync.aligned.m8n8.x4.shared.b16 {%0,%1,%2,%3}, [%4];"
        : "=r"(r[0]), "=r"(r[1]), "=r"(r[2]), "=r"(r[3]) : "r"(addr));
}
__device__ __forceinline__ uint32_t smem_u32(const void* p) {
    uint32_t a;
    asm("{ .reg .u64 t; cvta.to.shared.u64 t, %1; cvt.u32.u64 %0, t; }" : "=r"(a) : "l"(p));
    return a;
}
#define CP_ASYNC16(dst, src) \
    asm volatile("cp.async.cg.shared.global [%0], [%1], 16;" :: "r"(dst), "l"(src) : "memory")
#define CP_COMMIT()  asm volatile("cp.async.commit_group;" ::: "memory")
#define CP_WAIT0()   asm volatile("cp.async.wait_group 0;" ::: "memory")

// ---------------------------------------------------------------------------
// One-time W fragment split (fp16 hi/lo) in m16n8k16 B-fragment order.
// ---------------------------------------------------------------------------
__global__ __launch_bounds__(256)
void split_wfrag(const float* __restrict__ W1, const float* __restrict__ Wc1) {
    int t = blockIdx.x * 256 + threadIdx.x;       // 9*16*32*32 = 147456 total
    int lane = t & 31;
    int n8   = (t >> 5) & 31;
    int kc   = (t >> 10) & 15;
    int mat  = t >> 14;
    const float* W = (mat == 0) ? W1 : (Wc1 + (size_t)(mat - 1) * 65536);
    int k = kc * 16 + (lane & 3) * 2;
    int n = n8 * 8 + (lane >> 2);
    float v00 = W[(size_t)k * 256 + n];
    float v01 = W[(size_t)(k + 1) * 256 + n];
    float v10 = W[(size_t)(k + 8) * 256 + n];
    float v11 = W[(size_t)(k + 9) * 256 + n];
    float h00, l00, h01, l01, h10, l10, h11, l11;
    h_split(v00, h00, l00);
    h_split(v01, h01, l01);
    h_split(v10, h10, l10);
    h_split(v11, h11, l11);
    uint4 f;
    f.x = pack_h2(h00, h01);
    f.y = pack_h2(h10, h11);
    f.z = pack_h2(l00, l01);
    f.w = pack_h2(l10, l11);
    g_wfrag[t] = f;
}

// smem layout (bytes): A stages 2 x (hi 4KB | lo 4KB) = 16KB, B stages 2 x 8KB
#define SM_A(s)   ((s) * 8192)
#define SM_ALO_OFF 4096
#define SM_B(s)   (16384 + (s) * 8192)
#define SM_BYTES_MAIN 32768
#define SMEM_BYTES (SM_BYTES_MAIN + 1536)

__device__ __forceinline__ int a_off(int r, int c) {
    return r * 32 + ((c ^ ((r >> 2) & 1)) << 4);
}

// ---------------------------------------------------------------------------
// fp16 2-split (3-term) GEMM: Out[128 rows, nBase..+128) = relu(A@W + bias)
// Fused head-partial-logits in BOTH modes: root uses W2, experts use Wc2[c]
// slice; partials go to g_plog (root: all rows; gather: routed rows).
// ---------------------------------------------------------------------------
template<bool GATHER>
__global__ __launch_bounds__(256, 2)
void gemm_mma(const float* __restrict__ Ain,
              const float* __restrict__ ball,
              const float* __restrict__ Whead,
              float* __restrict__ Out)
{
    extern __shared__ char sm[];
    int* ridx = (int*)(sm + SM_BYTES_MAIN);
    float* W2s = (float*)(sm);   // reused after mainloop

    const int tid  = threadIdx.x;
    const int wid  = tid >> 5;
    const int lane = tid & 31;
    const int mBase = blockIdx.y * 128;
    const int nBase = blockIdx.x * 128;

    const float* A;
    const float* bias;
    const float* whead_src;
    int mat;
    if (GATHER) {
        const int c   = blockIdx.z;
        const int cnt = g_cnt[c];
        if (mBase >= cnt) return;
        A    = g_h;
        bias = ball + c * 256;
        mat  = 1 + c;
        whead_src = Whead + (size_t)c * 2048 + (size_t)nBase * 8;
        if (tid < 128) {
            int gi = mBase + tid;
            ridx[tid] = (gi < cnt) ? g_idx[c * Bn + gi] : -1;
        }
        __syncthreads();
    } else {
        A    = Ain;
        bias = ball;
        mat  = 0;
        whead_src = Whead + (size_t)nBase * 8;
    }

    const int ar = tid >> 1;
    const int ah = tid & 1;
    int grow = GATHER ? ridx[ar] : (mBase + ar);
    const bool aok = (!GATHER) || (grow >= 0);
    const float* ap = A + (size_t)(aok ? grow : 0) * 256 + ah * 8;
    const int aoff = a_off(ar, ah);

    const int bx16 = blockIdx.x * 16;
    const uint32_t smb = smem_u32(sm);

    const int warp_m = wid & 3;
    const int warp_n = wid >> 2;

    int lm_off[2];
    {
        int mt = lane >> 3;
        int kb2 = mt >> 1;
        #pragma unroll
        for (int i = 0; i < 2; i++) {
            int row = warp_m * 32 + i * 16 + (mt & 1) * 8 + (lane & 7);
            lm_off[i] = a_off(row, kb2);
        }
    }

    float acc[2][8][4];
    #pragma unroll
    for (int i = 0; i < 2; i++)
        #pragma unroll
        for (int j = 0; j < 8; j++)
            #pragma unroll
            for (int t = 0; t < 4; t++) acc[i][j][t] = 0.f;

    auto stageA = [&](int buf, const float4* v) {
        uint4 hi4, lo4;
        float h0, l0, h1, l1;
        h_split(v[0].x, h0, l0); h_split(v[0].y, h1, l1);
        hi4.x = pack_h2(h0, h1); lo4.x = pack_h2(l0, l1);
        h_split(v[0].z, h0, l0); h_split(v[0].w, h1, l1);
        hi4.y = pack_h2(h0, h1); lo4.y = pack_h2(l0, l1);
        h_split(v[1].x, h0, l0); h_split(v[1].y, h1, l1);
        hi4.z = pack_h2(h0, h1); lo4.z = pack_h2(l0, l1);
        h_split(v[1].z, h0, l0); h_split(v[1].w, h1, l1);
        hi4.w = pack_h2(h0, h1); lo4.w = pack_h2(l0, l1);
        *(uint4*)(sm + SM_A(buf) + aoff)              = hi4;
        *(uint4*)(sm + SM_A(buf) + SM_ALO_OFF + aoff) = lo4;
    };
    auto stageB = [&](int buf, int kb) {
        uint32_t dbase = smb + SM_B(buf);
        #pragma unroll
        for (int i = 0; i < 2; i++) {
            int t   = tid + i * 256;
            int ln  = t & 31;
            int n8l = t >> 5;
            const uint4* src = g_wfrag +
                ((size_t)(mat * 16 + kb) * 32 + bx16 + n8l) * 32 + ln;
            CP_ASYNC16(dbase + (uint32_t)t * 16, (const void*)src);
        }
        CP_COMMIT();
    };

    {
        float4 av[2];
        av[0] = aok ? *(const float4*)(ap)     : make_float4(0.f, 0.f, 0.f, 0.f);
        av[1] = aok ? *(const float4*)(ap + 4) : make_float4(0.f, 0.f, 0.f, 0.f);
        stageA(0, av);
        stageB(0, 0);
        CP_WAIT0();
        __syncthreads();
    }

    for (int kb = 0; kb < 16; kb++) {
        const int p = kb & 1;
        float4 nv[2];
        if (kb < 15) {
            stageB(p ^ 1, kb + 1);
            nv[0] = aok ? *(const float4*)(ap + (kb + 1) * 16)     : make_float4(0.f, 0.f, 0.f, 0.f);
            nv[1] = aok ? *(const float4*)(ap + (kb + 1) * 16 + 4) : make_float4(0.f, 0.f, 0.f, 0.f);
        }

        uint32_t ahf[2][4], alf[2][4];
        #pragma unroll
        for (int i = 0; i < 2; i++) {
            ldmatrix_x4(ahf[i], smb + SM_A(p) + lm_off[i]);
            ldmatrix_x4(alf[i], smb + SM_A(p) + SM_ALO_OFF + lm_off[i]);
        }

        const char* BST = sm + SM_B(p);
        #pragma unroll
        for (int j = 0; j < 8; j++) {
            uint4 bf = *(const uint4*)(BST + (((warp_n * 8 + j) * 32 + lane) << 4));
            #pragma unroll
            for (int i = 0; i < 2; i++) {
                mma_f16(acc[i][j], ahf[i], bf.x, bf.y);
                mma_f16(acc[i][j], ahf[i], bf.z, bf.w);
                mma_f16(acc[i][j], alf[i], bf.x, bf.y);
            }
        }

        if (kb < 15) {
            stageA(p ^ 1, nv);
            CP_WAIT0();
            __syncthreads();
        }
    }

    // ---- head-weight slice (128 cols x 8 cls) into smem (dead after mainloop)
    __syncthreads();
    if (tid < 256) {
        *(float4*)(W2s + tid * 4) = *(const float4*)(whead_src + tid * 4);
    }
    __syncthreads();

    // ---- epilogue: bias + relu, store; accumulate partial head logits
    const int g  = lane >> 2;
    const int tg = lane & 3;
    float plg[2][2][8];
    #pragma unroll
    for (int i = 0; i < 2; i++)
        #pragma unroll
        for (int h = 0; h < 2; h++)
            #pragma unroll
            for (int cls = 0; cls < 8; cls++) plg[i][h][cls] = 0.f;

    #pragma unroll
    for (int i = 0; i < 2; i++) {
        int rl0 = warp_m * 32 + i * 16 + g;
        int rl1 = rl0 + 8;
        int r0, r1;
        if (GATHER) { r0 = ridx[rl0]; r1 = ridx[rl1]; }
        else        { r0 = mBase + rl0; r1 = mBase + rl1; }
        #pragma unroll
        for (int j = 0; j < 8; j++) {
            int colL = warp_n * 64 + j * 8 + tg * 2;
            int col  = nBase + colL;
            float bv0 = __ldg(bias + col);
            float bv1 = __ldg(bias + col + 1);
            float2 v0 = make_float2(fmaxf(acc[i][j][0] + bv0, 0.f),
                                    fmaxf(acc[i][j][1] + bv1, 0.f));
            float2 v1 = make_float2(fmaxf(acc[i][j][2] + bv0, 0.f),
                                    fmaxf(acc[i][j][3] + bv1, 0.f));
            const float* w0 = W2s + colL * 8;
            const float* w1 = w0 + 8;
            if (!GATHER) {
                *(float2*)(Out + (size_t)r0 * 256 + col) = v0;
                *(float2*)(Out + (size_t)r1 * 256 + col) = v1;
                *(float2*)(g_h + (size_t)r0 * 256 + col) = v0;
                *(float2*)(g_h + (size_t)r1 * 256 + col) = v1;
                #pragma unroll
                for (int cls = 0; cls < 8; cls++) {
                    plg[i][0][cls] += v0.x * w0[cls] + v0.y * w1[cls];
                    plg[i][1][cls] += v1.x * w0[cls] + v1.y * w1[cls];
                }
            } else {
                if (r0 >= 0) {
                    *(float2*)(Out + (size_t)r0 * 256 + col) = v0;
                    #pragma unroll
                    for (int cls = 0; cls < 8; cls++)
                        plg[i][0][cls] += v0.x * w0[cls] + v0.y * w1[cls];
                }
                if (r1 >= 0) {
                    *(float2*)(Out + (size_t)r1 * 256 + col) = v1;
                    #pragma unroll
                    for (int cls = 0; cls < 8; cls++)
                        plg[i][1][cls] += v1.x * w0[cls] + v1.y * w1[cls];
                }
            }
        }
    }

    // reduce plg over the 4 tg-lanes, store partials
    #pragma unroll
    for (int i = 0; i < 2; i++)
        #pragma unroll
        for (int h = 0; h < 2; h++)
            #pragma unroll
            for (int cls = 0; cls < 8; cls++) {
                float v = plg[i][h][cls];
                v += __shfl_xor_sync(0xffffffffu, v, 1);
                v += __shfl_xor_sync(0xffffffffu, v, 2);
                plg[i][h][cls] = v;
            }
    if (tg == 0) {
        int q = blockIdx.x * 2 + warp_n;
        #pragma unroll
        for (int i = 0; i < 2; i++) {
            int rl0 = warp_m * 32 + i * 16 + g;
            int r0, r1;
            if (GATHER) { r0 = ridx[rl0]; r1 = ridx[rl0 + 8]; }
            else        { r0 = mBase + rl0; r1 = r0 + 8; }
            if (!GATHER || r0 >= 0) {
                float* p0 = &g_plog[q][r0][0];
                *(float4*)(p0)     = *(float4*)&plg[i][0][0];
                *(float4*)(p0 + 4) = *(float4*)&plg[i][0][4];
            }
            if (!GATHER || r1 >= 0) {
                float* p1 = &g_plog[q][r1][0];
                *(float4*)(p1)     = *(float4*)&plg[i][1][0];
                *(float4*)(p1 + 4) = *(float4*)&plg[i][1][4];
            }
        }
    }
}

// ---------------------------------------------------------------------------
// Routing: sum 4 partial-logit quarters, softmax, tau-mask argmax,
// warp-aggregated compaction (1 atomic per warp per class).
// ---------------------------------------------------------------------------
__global__ __launch_bounds__(256)
void route_kernel(const float* __restrict__ b2, const float* __restrict__ tau,
                  float* __restrict__ outLogits, float* __restrict__ outDepth)
{
    const int s = blockIdx.x * 256 + threadIdx.x;
    const int lane = threadIdx.x & 31;
    float lg[8];
    #pragma unroll
    for (int j = 0; j < 8; j++) lg[j] = __ldg(b2 + j);
    #pragma unroll
    for (int q = 0; q < 4; q++) {
        float4 p0 = *(const float4*)&g_plog[q][s][0];
        float4 p1 = *(const float4*)&g_plog[q][s][4];
        lg[0] += p0.x; lg[1] += p0.y; lg[2] += p0.z; lg[3] += p0.w;
        lg[4] += p1.x; lg[5] += p1.y; lg[6] += p1.z; lg[7] += p1.w;
    }
    float mx = -1e30f;
    #pragma unroll
    for (int j = 0; j < 8; j++) mx = fmaxf(mx, lg[j]);
    float e[8], ss = 0.f;
    #pragma unroll
    for (int j = 0; j < 8; j++) { e[j] = expf(lg[j] - mx); ss += e[j]; }
    float inv = 1.0f / ss;
    int best = -1; float bp = -1.f;
    #pragma unroll
    for (int j = 0; j < 8; j++) {
        float pj = e[j] * inv;
        if (pj >= __ldg(tau + j) && pj > bp) { bp = pj; best = j; }
    }
    float* lo = outLogits + (size_t)s * 8;
    *(float4*)(lo)     = make_float4(lg[0], lg[1], lg[2], lg[3]);
    *(float4*)(lo + 4) = make_float4(lg[4], lg[5], lg[6], lg[7]);
    outDepth[s] = (best >= 0) ? 1.0f : 0.0f;

    // warp-aggregated compaction
    #pragma unroll
    for (int c = 0; c < 8; c++) {
        unsigned mask = __ballot_sync(0xffffffffu, best == c);
        if (best == c) {
            int leader = __ffs(mask) - 1;
            int base = 0;
            if (lane == leader) base = atomicAdd(&g_cnt[c], __popc(mask));
            base = __shfl_sync(mask, base, leader);
            int pos = base + __popc(mask & ((1u << lane) - 1u));
            g_idx[c * Bn + pos] = s;
        }
    }
}

// ---------------------------------------------------------------------------
// Expert combine: routed samples get logits = sum of 4 partials + bc2[c].
// ---------------------------------------------------------------------------
__global__ __launch_bounds__(256)
void expert_combine(const float* __restrict__ bc2, float* __restrict__ outLogits)
{
    const int c   = blockIdx.y;
    const int cnt = g_cnt[c];
    const int i   = blockIdx.x * 256 + threadIdx.x;
    if (i >= cnt) return;
    const int s = g_idx[c * Bn + i];
    float lg[8];
    #pragma unroll
    for (int j = 0; j < 8; j++) lg[j] = __ldg(bc2 + c * 8 + j);
    #pragma unroll
    for (int q = 0; q < 4; q++) {
        float4 p0 = *(const float4*)&g_plog[q][s][0];
        float4 p1 = *(const float4*)&g_plog[q][s][4];
        lg[0] += p0.x; lg[1] += p0.y; lg[2] += p0.z; lg[3] += p0.w;
        lg[4] += p1.x; lg[5] += p1.y; lg[6] += p1.z; lg[7] += p1.w;
    }
    float* lo = outLogits + (size_t)s * 8;
    *(float4*)(lo)     = make_float4(lg[0], lg[1], lg[2], lg[3]);
    *(float4*)(lo + 4) = make_float4(lg[4], lg[5], lg[6], lg[7]);
}

// ---------------------------------------------------------------------------
extern "C" void kernel_launch(void* const* d_in, const int* in_sizes, int n_in,
                              void* d_out, int out_size)
{
    const float* x   = (const float*)d_in[0];
    const float* W1  = (const float*)d_in[1];
    const float* b1  = (const float*)d_in[2];
    const float* W2  = (const float*)d_in[3];
    const float* b2  = (const float*)d_in[4];
    const float* Wc1 = (const float*)d_in[5];
    const float* bc1 = (const float*)d_in[6];
    const float* Wc2 = (const float*)d_in[7];
    const float* bc2 = (const float*)d_in[8];
    const float* tau = (const float*)d_in[9];

    float* out       = (float*)d_out;
    float* outLogits = out;
    float* outH      = out + (size_t)Bn * Cc;
    float* outDepth  = out + (size_t)Bn * (Cc + Hh);

    static bool attr_done = false;
    if (!attr_done) {
        cudaFuncSetAttribute(gemm_mma<false>, cudaFuncAttributeMaxDynamicSharedMemorySize, SMEM_BYTES);
        cudaFuncSetAttribute(gemm_mma<true>,  cudaFuncAttributeMaxDynamicSharedMemorySize, SMEM_BYTES);
        attr_done = true;
    }

    zero_cnt_kernel<<<1, 32>>>();

    // One-time W fragment split (W1 + 8 experts)
    split_wfrag<<<(9 * 16 * 32 * 32) / 256, 256>>>(W1, Wc1);

    // Root: h = relu(x @ W1 + b1) -> outH + g_h, fused partial logits -> g_plog
    gemm_mma<false><<<dim3(2, Bn / 128, 1), 256, SMEM_BYTES>>>(x, b1, W2, outH);

    // Routing from partial logits (warp-aggregated compaction)
    route_kernel<<<Bn / 256, 256>>>(b2, tau, outLogits, outDepth);

    // Expert dense: gather from g_h, write routed rows of outH,
    // fused expert-head partials -> g_plog (routed rows only)
    gemm_mma<true><<<dim3(2, Bn / 128, Cc), 256, SMEM_BYTES>>>(nullptr, bc1, Wc2, outH);

    // Expert head combine for routed rows
    expert_combine<<<dim3(Bn / 256, Cc), 256>>>(bc2, outLogits);
}

// round 15
// speedup vs baseline: 1.8035x; 1.0073x over previous
#include <cuda_runtime.h>
#include <cuda_fp16.h>
#include <math.h>
#include <stdint.h>

#define Bn 131072
#define Dd 256
#define Hh 256
#define Cc 8

// ---------------- scratch (device globals; no allocs allowed) ----------------
__device__ int    g_cnt[Cc];
__device__ int    g_idx[Cc * Bn];
__device__ int    g_unr_cnt;
__device__ int    g_unr[Bn];
__device__ float  g_h[(size_t)Bn * Hh];          // root hidden (gather + unrouted-copy source)
__device__ uint4  g_wfrag[9 * 16 * 32 * 32];     // [mat][kc][n8][lane] = {b0hi,b1hi,b0lo,b1lo}
__device__ float  g_plog[4][Bn][8];              // partial logits per col-quarter (reused by experts)

__global__ void zero_cnt_kernel() {
    if (threadIdx.x < Cc) g_cnt[threadIdx.x] = 0;
    if (threadIdx.x == Cc) g_unr_cnt = 0;
}

// ---------------- helpers ----------------
__device__ __forceinline__ uint32_t pack_h2(float x, float y) {
    __half2 h = __floats2half2_rn(x, y);
    return *(uint32_t*)&h;
}
__device__ __forceinline__ void h_split(float x, float& hi, float& lo) {
    __half h = __float2half_rn(x);
    hi = __half2float(h);
    lo = x - hi;
}

__device__ __forceinline__ void mma_f16(float* d, const uint32_t* a, uint32_t b0, uint32_t b1) {
    asm("mma.sync.aligned.m16n8k16.row.col.f32.f16.f16.f32 "
        "{%0,%1,%2,%3}, {%4,%5,%6,%7}, {%8,%9}, {%0,%1,%2,%3};"
        : "+f"(d[0]), "+f"(d[1]), "+f"(d[2]), "+f"(d[3])
        : "r"(a[0]), "r"(a[1]), "r"(a[2]), "r"(a[3]), "r"(b0), "r"(b1));
}
__device__ __forceinline__ void ldmatrix_x4(uint32_t* r, uint32_t addr) {
    asm volatile("ldmatrix.sync.aligned.m8n8.x4.shared.b16 {%0,%1,%2,%3}, [%4];"
        : "=r"(r[0]), "=r"(r[1]), "=r"(r[2]), "=r"(r[3]) : "r"(addr));
}
__device__ __forceinline__ uint32_t smem_u32(const void* p) {
    uint32_t a;
    asm("{ .reg .u64 t; cvta.to.shared.u64 t, %1; cvt.u32.u64 %0, t; }" : "=r"(a) : "l"(p));
    return a;
}
#define CP_ASYNC16(dst, src) \
    asm volatile("cp.async.cg.shared.global [%0], [%1], 16;" :: "r"(dst), "l"(src) : "memory")
#define CP_COMMIT()  asm volatile("cp.async.commit_group;" ::: "memory")
#define CP_WAIT0()   asm volatile("cp.async.wait_group 0;" ::: "memory")

// ---------------------------------------------------------------------------
// One-time W fragment split (fp16 hi/lo) in m16n8k16 B-fragment order.
// ---------------------------------------------------------------------------
__global__ __launch_bounds__(256)
void split_wfrag(const float* __restrict__ W1, const float* __restrict__ Wc1) {
    int t = blockIdx.x * 256 + threadIdx.x;       // 9*16*32*32 = 147456 total
    int lane = t & 31;
    int n8   = (t >> 5) & 31;
    int kc   = (t >> 10) & 15;
    int mat  = t >> 14;
    const float* W = (mat == 0) ? W1 : (Wc1 + (size_t)(mat - 1) * 65536);
    int k = kc * 16 + (lane & 3) * 2;
    int n = n8 * 8 + (lane >> 2);
    float v00 = W[(size_t)k * 256 + n];
    float v01 = W[(size_t)(k + 1) * 256 + n];
    float v10 = W[(size_t)(k + 8) * 256 + n];
    float v11 = W[(size_t)(k + 9) * 256 + n];
    float h00, l00, h01, l01, h10, l10, h11, l11;
    h_split(v00, h00, l00);
    h_split(v01, h01, l01);
    h_split(v10, h10, l10);
    h_split(v11, h11, l11);
    uint4 f;
    f.x = pack_h2(h00, h01);
    f.y = pack_h2(h10, h11);
    f.z = pack_h2(l00, l01);
    f.w = pack_h2(l10, l11);
    g_wfrag[t] = f;
}

// smem layout (bytes): A stages 2 x (hi 4KB | lo 4KB) = 16KB, B stages 2 x 8KB
#define SM_A(s)   ((s) * 8192)
#define SM_ALO_OFF 4096
#define SM_B(s)   (16384 + (s) * 8192)
#define SM_BYTES_MAIN 32768
#define SMEM_BYTES (SM_BYTES_MAIN + 1536)

__device__ __forceinline__ int a_off(int r, int c) {
    return r * 32 + ((c ^ ((r >> 2) & 1)) << 4);
}

// ---------------------------------------------------------------------------
// fp16 2-split (3-term) GEMM: [128 rows, nBase..+128) = relu(A@W + bias)
// Root: writes g_h only + head partials (W2) -> g_plog.
// Gather: writes routed rows of Out + expert-head partials (Wc2) -> g_plog.
// ---------------------------------------------------------------------------
template<bool GATHER>
__global__ __launch_bounds__(256, 2)
void gemm_mma(const float* __restrict__ Ain,
              const float* __restrict__ ball,
              const float* __restrict__ Whead,
              float* __restrict__ Out)
{
    extern __shared__ char sm[];
    int* ridx = (int*)(sm + SM_BYTES_MAIN);
    float* W2s = (float*)(sm);   // reused after mainloop

    const int tid  = threadIdx.x;
    const int wid  = tid >> 5;
    const int lane = tid & 31;
    const int mBase = blockIdx.y * 128;
    const int nBase = blockIdx.x * 128;

    const float* A;
    const float* bias;
    const float* whead_src;
    int mat;
    if (GATHER) {
        const int c   = blockIdx.z;
        const int cnt = g_cnt[c];
        if (mBase >= cnt) return;
        A    = g_h;
        bias = ball + c * 256;
        mat  = 1 + c;
        whead_src = Whead + (size_t)c * 2048 + (size_t)nBase * 8;
        if (tid < 128) {
            int gi = mBase + tid;
            ridx[tid] = (gi < cnt) ? g_idx[c * Bn + gi] : -1;
        }
        __syncthreads();
    } else {
        A    = Ain;
        bias = ball;
        mat  = 0;
        whead_src = Whead + (size_t)nBase * 8;
    }

    const int ar = tid >> 1;
    const int ah = tid & 1;
    int grow = GATHER ? ridx[ar] : (mBase + ar);
    const bool aok = (!GATHER) || (grow >= 0);
    const float* ap = A + (size_t)(aok ? grow : 0) * 256 + ah * 8;
    const int aoff = a_off(ar, ah);

    const int bx16 = blockIdx.x * 16;
    const uint32_t smb = smem_u32(sm);

    const int warp_m = wid & 3;
    const int warp_n = wid >> 2;

    int lm_off[2];
    {
        int mt = lane >> 3;
        int kb2 = mt >> 1;
        #pragma unroll
        for (int i = 0; i < 2; i++) {
            int row = warp_m * 32 + i * 16 + (mt & 1) * 8 + (lane & 7);
            lm_off[i] = a_off(row, kb2);
        }
    }

    float acc[2][8][4];
    #pragma unroll
    for (int i = 0; i < 2; i++)
        #pragma unroll
        for (int j = 0; j < 8; j++)
            #pragma unroll
            for (int t = 0; t < 4; t++) acc[i][j][t] = 0.f;

    auto stageA = [&](int buf, const float4* v) {
        uint4 hi4, lo4;
        float h0, l0, h1, l1;
        h_split(v[0].x, h0, l0); h_split(v[0].y, h1, l1);
        hi4.x = pack_h2(h0, h1); lo4.x = pack_h2(l0, l1);
        h_split(v[0].z, h0, l0); h_split(v[0].w, h1, l1);
        hi4.y = pack_h2(h0, h1); lo4.y = pack_h2(l0, l1);
        h_split(v[1].x, h0, l0); h_split(v[1].y, h1, l1);
        hi4.z = pack_h2(h0, h1); lo4.z = pack_h2(l0, l1);
        h_split(v[1].z, h0, l0); h_split(v[1].w, h1, l1);
        hi4.w = pack_h2(h0, h1); lo4.w = pack_h2(l0, l1);
        *(uint4*)(sm + SM_A(buf) + aoff)              = hi4;
        *(uint4*)(sm + SM_A(buf) + SM_ALO_OFF + aoff) = lo4;
    };
    auto stageB = [&](int buf, int kb) {
        uint32_t dbase = smb + SM_B(buf);
        #pragma unroll
        for (int i = 0; i < 2; i++) {
            int t   = tid + i * 256;
            int ln  = t & 31;
            int n8l = t >> 5;
            const uint4* src = g_wfrag +
                ((size_t)(mat * 16 + kb) * 32 + bx16 + n8l) * 32 + ln;
            CP_ASYNC16(dbase + (uint32_t)t * 16, (const void*)src);
        }
        CP_COMMIT();
    };

    {
        float4 av[2];
        av[0] = aok ? *(const float4*)(ap)     : make_float4(0.f, 0.f, 0.f, 0.f);
        av[1] = aok ? *(const float4*)(ap + 4) : make_float4(0.f, 0.f, 0.f, 0.f);
        stageA(0, av);
        stageB(0, 0);
        CP_WAIT0();
        __syncthreads();
    }

    for (int kb = 0; kb < 16; kb++) {
        const int p = kb & 1;
        float4 nv[2];
        if (kb < 15) {
            stageB(p ^ 1, kb + 1);
            nv[0] = aok ? *(const float4*)(ap + (kb + 1) * 16)     : make_float4(0.f, 0.f, 0.f, 0.f);
            nv[1] = aok ? *(const float4*)(ap + (kb + 1) * 16 + 4) : make_float4(0.f, 0.f, 0.f, 0.f);
        }

        uint32_t ahf[2][4], alf[2][4];
        #pragma unroll
        for (int i = 0; i < 2; i++) {
            ldmatrix_x4(ahf[i], smb + SM_A(p) + lm_off[i]);
            ldmatrix_x4(alf[i], smb + SM_A(p) + SM_ALO_OFF + lm_off[i]);
        }

        const char* BST = sm + SM_B(p);
        #pragma unroll
        for (int j = 0; j < 8; j++) {
            uint4 bf = *(const uint4*)(BST + (((warp_n * 8 + j) * 32 + lane) << 4));
            #pragma unroll
            for (int i = 0; i < 2; i++) {
                mma_f16(acc[i][j], ahf[i], bf.x, bf.y);
                mma_f16(acc[i][j], ahf[i], bf.z, bf.w);
                mma_f16(acc[i][j], alf[i], bf.x, bf.y);
            }
        }

        if (kb < 15) {
            stageA(p ^ 1, nv);
            CP_WAIT0();
            __syncthreads();
        }
    }

    // ---- head-weight slice (128 cols x 8 cls) into smem (dead after mainloop)
    __syncthreads();
    if (tid < 256) {
        *(float4*)(W2s + tid * 4) = *(const float4*)(whead_src + tid * 4);
    }
    __syncthreads();

    // ---- epilogue: bias + relu, store; accumulate partial head logits
    const int g  = lane >> 2;
    const int tg = lane & 3;
    float plg[2][2][8];
    #pragma unroll
    for (int i = 0; i < 2; i++)
        #pragma unroll
        for (int h = 0; h < 2; h++)
            #pragma unroll
            for (int cls = 0; cls < 8; cls++) plg[i][h][cls] = 0.f;

    #pragma unroll
    for (int i = 0; i < 2; i++) {
        int rl0 = warp_m * 32 + i * 16 + g;
        int rl1 = rl0 + 8;
        int r0, r1;
        if (GATHER) { r0 = ridx[rl0]; r1 = ridx[rl1]; }
        else        { r0 = mBase + rl0; r1 = mBase + rl1; }
        #pragma unroll
        for (int j = 0; j < 8; j++) {
            int colL = warp_n * 64 + j * 8 + tg * 2;
            int col  = nBase + colL;
            float bv0 = __ldg(bias + col);
            float bv1 = __ldg(bias + col + 1);
            float2 v0 = make_float2(fmaxf(acc[i][j][0] + bv0, 0.f),
                                    fmaxf(acc[i][j][1] + bv1, 0.f));
            float2 v1 = make_float2(fmaxf(acc[i][j][2] + bv0, 0.f),
                                    fmaxf(acc[i][j][3] + bv1, 0.f));
            const float* w0 = W2s + colL * 8;
            const float* w1 = w0 + 8;
            if (!GATHER) {
                // root: h goes to g_h only (outH routed rows come from the
                // gather GEMM; unrouted rows from copy_unrouted)
                *(float2*)(g_h + (size_t)r0 * 256 + col) = v0;
                *(float2*)(g_h + (size_t)r1 * 256 + col) = v1;
                #pragma unroll
                for (int cls = 0; cls < 8; cls++) {
                    plg[i][0][cls] += v0.x * w0[cls] + v0.y * w1[cls];
                    plg[i][1][cls] += v1.x * w0[cls] + v1.y * w1[cls];
                }
            } else {
                if (r0 >= 0) {
                    *(float2*)(Out + (size_t)r0 * 256 + col) = v0;
                    #pragma unroll
                    for (int cls = 0; cls < 8; cls++)
                        plg[i][0][cls] += v0.x * w0[cls] + v0.y * w1[cls];
                }
                if (r1 >= 0) {
                    *(float2*)(Out + (size_t)r1 * 256 + col) = v1;
                    #pragma unroll
                    for (int cls = 0; cls < 8; cls++)
                        plg[i][1][cls] += v1.x * w0[cls] + v1.y * w1[cls];
                }
            }
        }
    }

    // reduce plg over the 4 tg-lanes, store partials
    #pragma unroll
    for (int i = 0; i < 2; i++)
        #pragma unroll
        for (int h = 0; h < 2; h++)
            #pragma unroll
            for (int cls = 0; cls < 8; cls++) {
                float v = plg[i][h][cls];
                v += __shfl_xor_sync(0xffffffffu, v, 1);
                v += __shfl_xor_sync(0xffffffffu, v, 2);
                plg[i][h][cls] = v;
            }
    if (tg == 0) {
        int q = blockIdx.x * 2 + warp_n;
        #pragma unroll
        for (int i = 0; i < 2; i++) {
            int rl0 = warp_m * 32 + i * 16 + g;
            int r0, r1;
            if (GATHER) { r0 = ridx[rl0]; r1 = ridx[rl0 + 8]; }
            else        { r0 = mBase + rl0; r1 = r0 + 8; }
            if (!GATHER || r0 >= 0) {
                float* p0 = &g_plog[q][r0][0];
                *(float4*)(p0)     = *(float4*)&plg[i][0][0];
                *(float4*)(p0 + 4) = *(float4*)&plg[i][0][4];
            }
            if (!GATHER || r1 >= 0) {
                float* p1 = &g_plog[q][r1][0];
                *(float4*)(p1)     = *(float4*)&plg[i][1][0];
                *(float4*)(p1 + 4) = *(float4*)&plg[i][1][4];
            }
        }
    }
}

// ---------------------------------------------------------------------------
// Routing: 2 threads per sample (each sums 2 partial quarters), shfl combine,
// softmax + tau-mask argmax on even lane, warp-aggregated compaction of both
// routed (per class) and unrouted lists.
// ---------------------------------------------------------------------------
__global__ __launch_bounds__(256)
void route_kernel(const float* __restrict__ b2, const float* __restrict__ tau,
                  float* __restrict__ outLogits, float* __restrict__ outDepth)
{
    const int t    = blockIdx.x * 256 + threadIdx.x;   // 2*Bn threads
    const int s    = t >> 1;
    const int half = t & 1;
    const int lane = threadIdx.x & 31;

    float lg[8];
    #pragma unroll
    for (int j = 0; j < 8; j++) lg[j] = 0.f;
    #pragma unroll
    for (int qi = 0; qi < 2; qi++) {
        int q = half * 2 + qi;
        float4 p0 = *(const float4*)&g_plog[q][s][0];
        float4 p1 = *(const float4*)&g_plog[q][s][4];
        lg[0] += p0.x; lg[1] += p0.y; lg[2] += p0.z; lg[3] += p0.w;
        lg[4] += p1.x; lg[5] += p1.y; lg[6] += p1.z; lg[7] += p1.w;
    }
    // combine halves (partner = lane^1)
    #pragma unroll
    for (int j = 0; j < 8; j++) lg[j] += __shfl_xor_sync(0xffffffffu, lg[j], 1);

    int best = -1;
    bool unrouted = false;
    if (half == 0) {
        float mx = -1e30f;
        #pragma unroll
        for (int j = 0; j < 8; j++) { lg[j] += __ldg(b2 + j); mx = fmaxf(mx, lg[j]); }
        float e[8], ss = 0.f;
        #pragma unroll
        for (int j = 0; j < 8; j++) { e[j] = expf(lg[j] - mx); ss += e[j]; }
        float inv = 1.0f / ss;
        float bp = -1.f;
        #pragma unroll
        for (int j = 0; j < 8; j++) {
            float pj = e[j] * inv;
            if (pj >= __ldg(tau + j) && pj > bp) { bp = pj; best = j; }
        }
        float* lo = outLogits + (size_t)s * 8;
        *(float4*)(lo)     = make_float4(lg[0], lg[1], lg[2], lg[3]);
        *(float4*)(lo + 4) = make_float4(lg[4], lg[5], lg[6], lg[7]);
        outDepth[s] = (best >= 0) ? 1.0f : 0.0f;
        unrouted = (best < 0);
    }

    // warp-aggregated compaction (odd lanes have best=-1, unrouted=false)
    #pragma unroll
    for (int c = 0; c < 8; c++) {
        unsigned mask = __ballot_sync(0xffffffffu, best == c);
        if (best == c) {
            int leader = __ffs(mask) - 1;
            int base = 0;
            if (lane == leader) base = atomicAdd(&g_cnt[c], __popc(mask));
            base = __shfl_sync(mask, base, leader);
            int pos = base + __popc(mask & ((1u << lane) - 1u));
            g_idx[c * Bn + pos] = s;
        }
    }
    {
        unsigned mask = __ballot_sync(0xffffffffu, unrouted);
        if (unrouted) {
            int leader = __ffs(mask) - 1;
            int base = 0;
            if (lane == leader) base = atomicAdd(&g_unr_cnt, __popc(mask));
            base = __shfl_sync(mask, base, leader);
            int pos = base + __popc(mask & ((1u << lane) - 1u));
            g_unr[pos] = s;
        }
    }
}

// ---------------------------------------------------------------------------
// Copy unrouted rows g_h -> outH (one warp per row, grid-strided).
// ---------------------------------------------------------------------------
__global__ __launch_bounds__(256)
void copy_unrouted(float* __restrict__ outH)
{
    const int lane = threadIdx.x & 31;
    const int wid  = threadIdx.x >> 5;
    const int cnt  = g_unr_cnt;
    for (int r = blockIdx.x * 8 + wid; r < cnt; r += gridDim.x * 8) {
        int s = g_unr[r];
        const float4* src = (const float4*)(g_h + (size_t)s * 256);
        float4*       dst = (float4*)(outH + (size_t)s * 256);
        dst[lane]      = src[lane];
        dst[lane + 32] = src[lane + 32];
    }
}

// ---------------------------------------------------------------------------
// Expert combine: routed samples get logits = sum of 4 partials + bc2[c].
// ---------------------------------------------------------------------------
__global__ __launch_bounds__(256)
void expert_combine(const float* __restrict__ bc2, float* __restrict__ outLogits)
{
    const int c   = blockIdx.y;
    const int cnt = g_cnt[c];
    const int i   = blockIdx.x * 256 + threadIdx.x;
    if (i >= cnt) return;
    const int s = g_idx[c * Bn + i];
    float lg[8];
    #pragma unroll
    for (int j = 0; j < 8; j++) lg[j] = __ldg(bc2 + c * 8 + j);
    #pragma unroll
    for (int q = 0; q < 4; q++) {
        float4 p0 = *(const float4*)&g_plog[q][s][0];
        float4 p1 = *(const float4*)&g_plog[q][s][4];
        lg[0] += p0.x; lg[1] += p0.y; lg[2] += p0.z; lg[3] += p0.w;
        lg[4] += p1.x; lg[5] += p1.y; lg[6] += p1.z; lg[7] += p1.w;
    }
    float* lo = outLogits + (size_t)s * 8;
    *(float4*)(lo)     = make_float4(lg[0], lg[1], lg[2], lg[3]);
    *(float4*)(lo + 4) = make_float4(lg[4], lg[5], lg[6], lg[7]);
}

// ---------------------------------------------------------------------------
extern "C" void kernel_launch(void* const* d_in, const int* in_sizes, int n_in,
                              void* d_out, int out_size)
{
    const float* x   = (const float*)d_in[0];
    const float* W1  = (const float*)d_in[1];
    const float* b1  = (const float*)d_in[2];
    const float* W2  = (const float*)d_in[3];
    const float* b2  = (const float*)d_in[4];
    const float* Wc1 = (const float*)d_in[5];
    const float* bc1 = (const float*)d_in[6];
    const float* Wc2 = (const float*)d_in[7];
    const float* bc2 = (const float*)d_in[8];
    const float* tau = (const float*)d_in[9];

    float* out       = (float*)d_out;
    float* outLogits = out;
    float* outH      = out + (size_t)Bn * Cc;
    float* outDepth  = out + (size_t)Bn * (Cc + Hh);

    static bool attr_done = false;
    if (!attr_done) {
        cudaFuncSetAttribute(gemm_mma<false>, cudaFuncAttributeMaxDynamicSharedMemorySize, SMEM_BYTES);
        cudaFuncSetAttribute(gemm_mma<true>,  cudaFuncAttributeMaxDynamicSharedMemorySize, SMEM_BYTES);
        attr_done = true;
    }

    zero_cnt_kernel<<<1, 32>>>();

    // One-time W fragment split (W1 + 8 experts)
    split_wfrag<<<(9 * 16 * 32 * 32) / 256, 256>>>(W1, Wc1);

    // Root: h = relu(x @ W1 + b1) -> g_h, fused head partials -> g_plog
    gemm_mma<false><<<dim3(2, Bn / 128, 1), 256, SMEM_BYTES>>>(x, b1, W2, outH);

    // Routing from partial logits (2 threads/sample) + routed/unrouted lists
    route_kernel<<<(2 * Bn) / 256, 256>>>(b2, tau, outLogits, outDepth);

    // Unrouted rows: outH = h
    copy_unrouted<<<1024, 256>>>(outH);

    // Expert dense: gather from g_h, write routed rows of outH,
    // fused expert-head partials -> g_plog (routed rows only)
    gemm_mma<true><<<dim3(2, Bn / 128, Cc), 256, SMEM_BYTES>>>(nullptr, bc1, Wc2, outH);

    // Expert head combine for routed rows
    expert_combine<<<dim3(Bn / 256, Cc), 256>>>(bc2, outLogits);
}

// round 16
// speedup vs baseline: 1.8566x; 1.0294x over previous
#include <cuda_runtime.h>
#include <cuda_fp16.h>
#include <math.h>
#include <stdint.h>

#define Bn 131072
#define Dd 256
#define Hh 256
#define Cc 8

// ---------------- scratch (device globals; no allocs allowed) ----------------
__device__ int    g_cnt[Cc];
__device__ int    g_idx[Cc * Bn];
__device__ int    g_unr_cnt;
__device__ int    g_unr[Bn];
__device__ float  g_h[(size_t)Bn * Hh];          // root hidden (gather + unrouted-copy source)
__device__ uint4  g_wfrag[9 * 16 * 32 * 32];     // [mat][kc][n8][lane] = {b0hi,b1hi,b0lo,b1lo}
__device__ float  g_plog[(size_t)Bn * 32];       // [s][q][8] partial logits (contiguous/sample)

__global__ void zero_cnt_kernel() {
    if (threadIdx.x < Cc) g_cnt[threadIdx.x] = 0;
    if (threadIdx.x == Cc) g_unr_cnt = 0;
}

// ---------------- helpers ----------------
__device__ __forceinline__ uint32_t pack_h2(float x, float y) {
    __half2 h = __floats2half2_rn(x, y);
    return *(uint32_t*)&h;
}
__device__ __forceinline__ void h_split(float x, float& hi, float& lo) {
    __half h = __float2half_rn(x);
    hi = __half2float(h);
    lo = x - hi;
}

__device__ __forceinline__ void mma_f16(float* d, const uint32_t* a, uint32_t b0, uint32_t b1) {
    asm("mma.sync.aligned.m16n8k16.row.col.f32.f16.f16.f32 "
        "{%0,%1,%2,%3}, {%4,%5,%6,%7}, {%8,%9}, {%0,%1,%2,%3};"
        : "+f"(d[0]), "+f"(d[1]), "+f"(d[2]), "+f"(d[3])
        : "r"(a[0]), "r"(a[1]), "r"(a[2]), "r"(a[3]), "r"(b0), "r"(b1));
}
__device__ __forceinline__ void ldmatrix_x4(uint32_t* r, uint32_t addr) {
    asm volatile("ldmatrix.sync.aligned.m8n8.x4.shared.b16 {%0,%1,%2,%3}, [%4];"
        : "=r"(r[0]), "=r"(r[1]), "=r"(r[2]), "=r"(r[3]) : "r"(addr));
}
__device__ __forceinline__ uint32_t smem_u32(const void* p) {
    uint32_t a;
    asm("{ .reg .u64 t; cvta.to.shared.u64 t, %1; cvt.u32.u64 %0, t; }" : "=r"(a) : "l"(p));
    return a;
}
#define CP_ASYNC16(dst, src) \
    asm volatile("cp.async.cg.shared.global [%0], [%1], 16;" :: "r"(dst), "l"(src) : "memory")
#define CP_COMMIT()  asm volatile("cp.async.commit_group;" ::: "memory")
#define CP_WAIT0()   asm volatile("cp.async.wait_group 0;" ::: "memory")

// ---------------------------------------------------------------------------
// One-time W fragment split (fp16 hi/lo) in m16n8k16 B-fragment order.
// ---------------------------------------------------------------------------
__global__ __launch_bounds__(256)
void split_wfrag(const float* __restrict__ W1, const float* __restrict__ Wc1) {
    int t = blockIdx.x * 256 + threadIdx.x;       // 9*16*32*32 = 147456 total
    int lane = t & 31;
    int n8   = (t >> 5) & 31;
    int kc   = (t >> 10) & 15;
    int mat  = t >> 14;
    const float* W = (mat == 0) ? W1 : (Wc1 + (size_t)(mat - 1) * 65536);
    int k = kc * 16 + (lane & 3) * 2;
    int n = n8 * 8 + (lane >> 2);
    float v00 = W[(size_t)k * 256 + n];
    float v01 = W[(size_t)(k + 1) * 256 + n];
    float v10 = W[(size_t)(k + 8) * 256 + n];
    float v11 = W[(size_t)(k + 9) * 256 + n];
    float h00, l00, h01, l01, h10, l10, h11, l11;
    h_split(v00, h00, l00);
    h_split(v01, h01, l01);
    h_split(v10, h10, l10);
    h_split(v11, h11, l11);
    uint4 f;
    f.x = pack_h2(h00, h01);
    f.y = pack_h2(h10, h11);
    f.z = pack_h2(l00, l01);
    f.w = pack_h2(l10, l11);
    g_wfrag[t] = f;
}

// smem layout (bytes): A stages 2 x (hi 4KB | lo 4KB) = 16KB, B stages 2 x 8KB
#define SM_A(s)   ((s) * 8192)
#define SM_ALO_OFF 4096
#define SM_B(s)   (16384 + (s) * 8192)
#define SM_BYTES_MAIN 32768
#define SMEM_BYTES (SM_BYTES_MAIN + 1536)

__device__ __forceinline__ int a_off(int r, int c) {
    return r * 32 + ((c ^ ((r >> 2) & 1)) << 4);
}

// ---------------------------------------------------------------------------
// fp16 2-split (3-term) GEMM: [128 rows, nBase..+128) = relu(A@W + bias)
// Root: writes g_h only + head partials (W2) -> g_plog.
// Gather: writes routed rows of Out + expert-head partials (Wc2) -> g_plog.
// ---------------------------------------------------------------------------
template<bool GATHER>
__global__ __launch_bounds__(256, 2)
void gemm_mma(const float* __restrict__ Ain,
              const float* __restrict__ ball,
              const float* __restrict__ Whead,
              float* __restrict__ Out)
{
    extern __shared__ char sm[];
    int* ridx = (int*)(sm + SM_BYTES_MAIN);
    float* W2s = (float*)(sm);   // reused after mainloop

    const int tid  = threadIdx.x;
    const int wid  = tid >> 5;
    const int lane = tid & 31;
    const int mBase = blockIdx.y * 128;
    const int nBase = blockIdx.x * 128;

    const float* A;
    const float* bias;
    const float* whead_src;
    int mat;
    if (GATHER) {
        const int c   = blockIdx.z;
        const int cnt = g_cnt[c];
        if (mBase >= cnt) return;
        A    = g_h;
        bias = ball + c * 256;
        mat  = 1 + c;
        whead_src = Whead + (size_t)c * 2048 + (size_t)nBase * 8;
        if (tid < 128) {
            int gi = mBase + tid;
            ridx[tid] = (gi < cnt) ? g_idx[c * Bn + gi] : -1;
        }
        __syncthreads();
    } else {
        A    = Ain;
        bias = ball;
        mat  = 0;
        whead_src = Whead + (size_t)nBase * 8;
    }

    const int ar = tid >> 1;
    const int ah = tid & 1;
    int grow = GATHER ? ridx[ar] : (mBase + ar);
    const bool aok = (!GATHER) || (grow >= 0);
    const float* ap = A + (size_t)(aok ? grow : 0) * 256 + ah * 8;
    const int aoff = a_off(ar, ah);

    const int bx16 = blockIdx.x * 16;
    const uint32_t smb = smem_u32(sm);

    const int warp_m = wid & 3;
    const int warp_n = wid >> 2;

    int lm_off[2];
    {
        int mt = lane >> 3;
        int kb2 = mt >> 1;
        #pragma unroll
        for (int i = 0; i < 2; i++) {
            int row = warp_m * 32 + i * 16 + (mt & 1) * 8 + (lane & 7);
            lm_off[i] = a_off(row, kb2);
        }
    }

    float acc[2][8][4];
    #pragma unroll
    for (int i = 0; i < 2; i++)
        #pragma unroll
        for (int j = 0; j < 8; j++)
            #pragma unroll
            for (int t = 0; t < 4; t++) acc[i][j][t] = 0.f;

    auto stageA = [&](int buf, const float4* v) {
        uint4 hi4, lo4;
        float h0, l0, h1, l1;
        h_split(v[0].x, h0, l0); h_split(v[0].y, h1, l1);
        hi4.x = pack_h2(h0, h1); lo4.x = pack_h2(l0, l1);
        h_split(v[0].z, h0, l0); h_split(v[0].w, h1, l1);
        hi4.y = pack_h2(h0, h1); lo4.y = pack_h2(l0, l1);
        h_split(v[1].x, h0, l0); h_split(v[1].y, h1, l1);
        hi4.z = pack_h2(h0, h1); lo4.z = pack_h2(l0, l1);
        h_split(v[1].z, h0, l0); h_split(v[1].w, h1, l1);
        hi4.w = pack_h2(h0, h1); lo4.w = pack_h2(l0, l1);
        *(uint4*)(sm + SM_A(buf) + aoff)              = hi4;
        *(uint4*)(sm + SM_A(buf) + SM_ALO_OFF + aoff) = lo4;
    };
    auto stageB = [&](int buf, int kb) {
        uint32_t dbase = smb + SM_B(buf);
        #pragma unroll
        for (int i = 0; i < 2; i++) {
            int t   = tid + i * 256;
            int ln  = t & 31;
            int n8l = t >> 5;
            const uint4* src = g_wfrag +
                ((size_t)(mat * 16 + kb) * 32 + bx16 + n8l) * 32 + ln;
            CP_ASYNC16(dbase + (uint32_t)t * 16, (const void*)src);
        }
        CP_COMMIT();
    };

    {
        float4 av[2];
        av[0] = aok ? *(const float4*)(ap)     : make_float4(0.f, 0.f, 0.f, 0.f);
        av[1] = aok ? *(const float4*)(ap + 4) : make_float4(0.f, 0.f, 0.f, 0.f);
        stageA(0, av);
        stageB(0, 0);
        CP_WAIT0();
        __syncthreads();
    }

    for (int kb = 0; kb < 16; kb++) {
        const int p = kb & 1;
        float4 nv[2];
        if (kb < 15) {
            stageB(p ^ 1, kb + 1);
            nv[0] = aok ? *(const float4*)(ap + (kb + 1) * 16)     : make_float4(0.f, 0.f, 0.f, 0.f);
            nv[1] = aok ? *(const float4*)(ap + (kb + 1) * 16 + 4) : make_float4(0.f, 0.f, 0.f, 0.f);
        }

        uint32_t ahf[2][4], alf[2][4];
        #pragma unroll
        for (int i = 0; i < 2; i++) {
            ldmatrix_x4(ahf[i], smb + SM_A(p) + lm_off[i]);
            ldmatrix_x4(alf[i], smb + SM_A(p) + SM_ALO_OFF + lm_off[i]);
        }

        const char* BST = sm + SM_B(p);
        #pragma unroll
        for (int j = 0; j < 8; j++) {
            uint4 bf = *(const uint4*)(BST + (((warp_n * 8 + j) * 32 + lane) << 4));
            #pragma unroll
            for (int i = 0; i < 2; i++) {
                mma_f16(acc[i][j], ahf[i], bf.x, bf.y);
                mma_f16(acc[i][j], ahf[i], bf.z, bf.w);
                mma_f16(acc[i][j], alf[i], bf.x, bf.y);
            }
        }

        if (kb < 15) {
            stageA(p ^ 1, nv);
            CP_WAIT0();
            __syncthreads();
        }
    }

    // ---- head-weight slice (128 cols x 8 cls) into smem (dead after mainloop)
    __syncthreads();
    if (tid < 256) {
        *(float4*)(W2s + tid * 4) = *(const float4*)(whead_src + tid * 4);
    }
    __syncthreads();

    // ---- epilogue: bias + relu, store; accumulate partial head logits
    const int g  = lane >> 2;
    const int tg = lane & 3;
    float plg[2][2][8];
    #pragma unroll
    for (int i = 0; i < 2; i++)
        #pragma unroll
        for (int h = 0; h < 2; h++)
            #pragma unroll
            for (int cls = 0; cls < 8; cls++) plg[i][h][cls] = 0.f;

    #pragma unroll
    for (int i = 0; i < 2; i++) {
        int rl0 = warp_m * 32 + i * 16 + g;
        int rl1 = rl0 + 8;
        int r0, r1;
        if (GATHER) { r0 = ridx[rl0]; r1 = ridx[rl1]; }
        else        { r0 = mBase + rl0; r1 = mBase + rl1; }
        #pragma unroll
        for (int j = 0; j < 8; j++) {
            int colL = warp_n * 64 + j * 8 + tg * 2;
            int col  = nBase + colL;
            float bv0 = __ldg(bias + col);
            float bv1 = __ldg(bias + col + 1);
            float2 v0 = make_float2(fmaxf(acc[i][j][0] + bv0, 0.f),
                                    fmaxf(acc[i][j][1] + bv1, 0.f));
            float2 v1 = make_float2(fmaxf(acc[i][j][2] + bv0, 0.f),
                                    fmaxf(acc[i][j][3] + bv1, 0.f));
            const float* w0 = W2s + colL * 8;
            const float* w1 = w0 + 8;
            if (!GATHER) {
                *(float2*)(g_h + (size_t)r0 * 256 + col) = v0;
                *(float2*)(g_h + (size_t)r1 * 256 + col) = v1;
                #pragma unroll
                for (int cls = 0; cls < 8; cls++) {
                    plg[i][0][cls] += v0.x * w0[cls] + v0.y * w1[cls];
                    plg[i][1][cls] += v1.x * w0[cls] + v1.y * w1[cls];
                }
            } else {
                if (r0 >= 0) {
                    *(float2*)(Out + (size_t)r0 * 256 + col) = v0;
                    #pragma unroll
                    for (int cls = 0; cls < 8; cls++)
                        plg[i][0][cls] += v0.x * w0[cls] + v0.y * w1[cls];
                }
                if (r1 >= 0) {
                    *(float2*)(Out + (size_t)r1 * 256 + col) = v1;
                    #pragma unroll
                    for (int cls = 0; cls < 8; cls++)
                        plg[i][1][cls] += v1.x * w0[cls] + v1.y * w1[cls];
                }
            }
        }
    }

    // reduce plg over the 4 tg-lanes, store partials (layout [s][q][8])
    #pragma unroll
    for (int i = 0; i < 2; i++)
        #pragma unroll
        for (int h = 0; h < 2; h++)
            #pragma unroll
            for (int cls = 0; cls < 8; cls++) {
                float v = plg[i][h][cls];
                v += __shfl_xor_sync(0xffffffffu, v, 1);
                v += __shfl_xor_sync(0xffffffffu, v, 2);
                plg[i][h][cls] = v;
            }
    if (tg == 0) {
        int q = blockIdx.x * 2 + warp_n;
        #pragma unroll
        for (int i = 0; i < 2; i++) {
            int rl0 = warp_m * 32 + i * 16 + g;
            int r0, r1;
            if (GATHER) { r0 = ridx[rl0]; r1 = ridx[rl0 + 8]; }
            else        { r0 = mBase + rl0; r1 = r0 + 8; }
            if (!GATHER || r0 >= 0) {
                float* p0 = g_plog + (size_t)r0 * 32 + q * 8;
                *(float4*)(p0)     = *(float4*)&plg[i][0][0];
                *(float4*)(p0 + 4) = *(float4*)&plg[i][0][4];
            }
            if (!GATHER || r1 >= 0) {
                float* p1 = g_plog + (size_t)r1 * 32 + q * 8;
                *(float4*)(p1)     = *(float4*)&plg[i][1][0];
                *(float4*)(p1 + 4) = *(float4*)&plg[i][1][4];
            }
        }
    }
}

// ---------------------------------------------------------------------------
// Routing: 1 thread/sample; 128B contiguous partial read; softmax, tau-mask
// argmax; warp-aggregated compaction of routed (per class) + unrouted lists.
// ---------------------------------------------------------------------------
__global__ __launch_bounds__(256)
void route_kernel(const float* __restrict__ b2, const float* __restrict__ tau,
                  float* __restrict__ outLogits, float* __restrict__ outDepth)
{
    const int s    = blockIdx.x * 256 + threadIdx.x;
    const int lane = threadIdx.x & 31;

    const float4* pp = (const float4*)(g_plog + (size_t)s * 32);
    float lg[8];
    #pragma unroll
    for (int j = 0; j < 8; j++) lg[j] = __ldg(b2 + j);
    #pragma unroll
    for (int q = 0; q < 4; q++) {
        float4 p0 = pp[q * 2];
        float4 p1 = pp[q * 2 + 1];
        lg[0] += p0.x; lg[1] += p0.y; lg[2] += p0.z; lg[3] += p0.w;
        lg[4] += p1.x; lg[5] += p1.y; lg[6] += p1.z; lg[7] += p1.w;
    }
    float mx = -1e30f;
    #pragma unroll
    for (int j = 0; j < 8; j++) mx = fmaxf(mx, lg[j]);
    float e[8], ss = 0.f;
    #pragma unroll
    for (int j = 0; j < 8; j++) { e[j] = expf(lg[j] - mx); ss += e[j]; }
    float inv = 1.0f / ss;
    int best = -1; float bp = -1.f;
    #pragma unroll
    for (int j = 0; j < 8; j++) {
        float pj = e[j] * inv;
        if (pj >= __ldg(tau + j) && pj > bp) { bp = pj; best = j; }
    }
    float* lo = outLogits + (size_t)s * 8;
    *(float4*)(lo)     = make_float4(lg[0], lg[1], lg[2], lg[3]);
    *(float4*)(lo + 4) = make_float4(lg[4], lg[5], lg[6], lg[7]);
    outDepth[s] = (best >= 0) ? 1.0f : 0.0f;

    // warp-aggregated compaction
    #pragma unroll
    for (int c = 0; c < 8; c++) {
        unsigned mask = __ballot_sync(0xffffffffu, best == c);
        if (best == c) {
            int leader = __ffs(mask) - 1;
            int base = 0;
            if (lane == leader) base = atomicAdd(&g_cnt[c], __popc(mask));
            base = __shfl_sync(mask, base, leader);
            int pos = base + __popc(mask & ((1u << lane) - 1u));
            g_idx[c * Bn + pos] = s;
        }
    }
    {
        bool unrouted = (best < 0);
        unsigned mask = __ballot_sync(0xffffffffu, unrouted);
        if (unrouted) {
            int leader = __ffs(mask) - 1;
            int base = 0;
            if (lane == leader) base = atomicAdd(&g_unr_cnt, __popc(mask));
            base = __shfl_sync(mask, base, leader);
            int pos = base + __popc(mask & ((1u << lane) - 1u));
            g_unr[pos] = s;
        }
    }
}

// ---------------------------------------------------------------------------
// Copy unrouted rows g_h -> outH (one warp per row, grid-strided).
// ---------------------------------------------------------------------------
__global__ __launch_bounds__(256)
void copy_unrouted(float* __restrict__ outH)
{
    const int lane = threadIdx.x & 31;
    const int wid  = threadIdx.x >> 5;
    const int cnt  = g_unr_cnt;
    for (int r = blockIdx.x * 8 + wid; r < cnt; r += gridDim.x * 8) {
        int s = g_unr[r];
        const float4* src = (const float4*)(g_h + (size_t)s * 256);
        float4*       dst = (float4*)(outH + (size_t)s * 256);
        dst[lane]      = src[lane];
        dst[lane + 32] = src[lane + 32];
    }
}

// ---------------------------------------------------------------------------
// Expert combine: routed samples get logits = sum of 4 partials + bc2[c].
// ---------------------------------------------------------------------------
__global__ __launch_bounds__(256)
void expert_combine(const float* __restrict__ bc2, float* __restrict__ outLogits)
{
    const int c   = blockIdx.y;
    const int cnt = g_cnt[c];
    const int i   = blockIdx.x * 256 + threadIdx.x;
    if (i >= cnt) return;
    const int s = g_idx[c * Bn + i];
    const float4* pp = (const float4*)(g_plog + (size_t)s * 32);
    float lg[8];
    #pragma unroll
    for (int j = 0; j < 8; j++) lg[j] = __ldg(bc2 + c * 8 + j);
    #pragma unroll
    for (int q = 0; q < 4; q++) {
        float4 p0 = pp[q * 2];
        float4 p1 = pp[q * 2 + 1];
        lg[0] += p0.x; lg[1] += p0.y; lg[2] += p0.z; lg[3] += p0.w;
        lg[4] += p1.x; lg[5] += p1.y; lg[6] += p1.z; lg[7] += p1.w;
    }
    float* lo = outLogits + (size_t)s * 8;
    *(float4*)(lo)     = make_float4(lg[0], lg[1], lg[2], lg[3]);
    *(float4*)(lo + 4) = make_float4(lg[4], lg[5], lg[6], lg[7]);
}

// ---------------------------------------------------------------------------
extern "C" void kernel_launch(void* const* d_in, const int* in_sizes, int n_in,
                              void* d_out, int out_size)
{
    const float* x   = (const float*)d_in[0];
    const float* W1  = (const float*)d_in[1];
    const float* b1  = (const float*)d_in[2];
    const float* W2  = (const float*)d_in[3];
    const float* b2  = (const float*)d_in[4];
    const float* Wc1 = (const float*)d_in[5];
    const float* bc1 = (const float*)d_in[6];
    const float* Wc2 = (const float*)d_in[7];
    const float* bc2 = (const float*)d_in[8];
    const float* tau = (const float*)d_in[9];

    float* out       = (float*)d_out;
    float* outLogits = out;
    float* outH      = out + (size_t)Bn * Cc;
    float* outDepth  = out + (size_t)Bn * (Cc + Hh);

    static bool attr_done = false;
    if (!attr_done) {
        cudaFuncSetAttribute(gemm_mma<false>, cudaFuncAttributeMaxDynamicSharedMemorySize, SMEM_BYTES);
        cudaFuncSetAttribute(gemm_mma<true>,  cudaFuncAttributeMaxDynamicSharedMemorySize, SMEM_BYTES);
        attr_done = true;
    }

    zero_cnt_kernel<<<1, 32>>>();

    // One-time W fragment split (W1 + 8 experts)
    split_wfrag<<<(9 * 16 * 32 * 32) / 256, 256>>>(W1, Wc1);

    // Root: h = relu(x @ W1 + b1) -> g_h, fused head partials -> g_plog
    gemm_mma<false><<<dim3(2, Bn / 128, 1), 256, SMEM_BYTES>>>(x, b1, W2, outH);

    // Routing from partial logits (1 thread/sample, contiguous reads)
    route_kernel<<<Bn / 256, 256>>>(b2, tau, outLogits, outDepth);

    // Unrouted rows: outH = h
    copy_unrouted<<<1024, 256>>>(outH);

    // Expert dense: gather from g_h, write routed rows of outH,
    // fused expert-head partials -> g_plog (routed rows only)
    gemm_mma<true><<<dim3(2, Bn / 128, Cc), 256, SMEM_BYTES>>>(nullptr, bc1, Wc2, outH);

    // Expert head combine for routed rows
    expert_combine<<<dim3(Bn / 256, Cc), 256>>>(bc2, outLogits);
}

// round 17
// speedup vs baseline: 1.8599x; 1.0018x over previous
#include <cuda_runtime.h>
#include <cuda_fp16.h>
#include <math.h>
#include <stdint.h>

#define Bn 131072
#define Dd 256
#define Hh 256
#define Cc 8

// ---------------- scratch (device globals; no allocs allowed) ----------------
__device__ int    g_cnt[Cc];
__device__ int    g_idx[Cc * Bn];
__device__ int    g_unr_cnt;
__device__ int    g_unr[Bn];
__device__ float  g_h[(size_t)Bn * Hh];          // root hidden (gather + unrouted-copy source)
__device__ uint4  g_wfrag[9 * 16 * 32 * 32];     // [mat][kc][n8][lane] = {b0hi,b1hi,b0lo,b1lo}
__device__ float  g_plog[(size_t)Bn * 32];       // [s][q][8] partial logits (contiguous/sample)

// ---------------- helpers ----------------
__device__ __forceinline__ uint32_t pack_h2(float x, float y) {
    __half2 h = __floats2half2_rn(x, y);
    return *(uint32_t*)&h;
}
__device__ __forceinline__ void h_split(float x, float& hi, float& lo) {
    __half h = __float2half_rn(x);
    hi = __half2float(h);
    lo = x - hi;
}

__device__ __forceinline__ void mma_f16(float* d, const uint32_t* a, uint32_t b0, uint32_t b1) {
    asm("mma.sync.aligned.m16n8k16.row.col.f32.f16.f16.f32 "
        "{%0,%1,%2,%3}, {%4,%5,%6,%7}, {%8,%9}, {%0,%1,%2,%3};"
        : "+f"(d[0]), "+f"(d[1]), "+f"(d[2]), "+f"(d[3])
        : "r"(a[0]), "r"(a[1]), "r"(a[2]), "r"(a[3]), "r"(b0), "r"(b1));
}
__device__ __forceinline__ void ldmatrix_x4(uint32_t* r, uint32_t addr) {
    asm volatile("ldmatrix.sync.aligned.m8n8.x4.shared.b16 {%0,%1,%2,%3}, [%4];"
        : "=r"(r[0]), "=r"(r[1]), "=r"(r[2]), "=r"(r[3]) : "r"(addr));
}
__device__ __forceinline__ uint32_t smem_u32(const void* p) {
    uint32_t a;
    asm("{ .reg .u64 t; cvta.to.shared.u64 t, %1; cvt.u32.u64 %0, t; }" : "=r"(a) : "l"(p));
    return a;
}
#define CP_ASYNC16(dst, src) \
    asm volatile("cp.async.cg.shared.global [%0], [%1], 16;" :: "r"(dst), "l"(src) : "memory")
#define CP_COMMIT()  asm volatile("cp.async.commit_group;" ::: "memory")
#define CP_WAIT0()   asm volatile("cp.async.wait_group 0;" ::: "memory")

// ---------------------------------------------------------------------------
// One-time W fragment split (fp16 hi/lo) in m16n8k16 B-fragment order.
// Block 0 also zeroes the routing counters (replaces zero_cnt kernel).
// ---------------------------------------------------------------------------
__global__ __launch_bounds__(256)
void split_wfrag(const float* __restrict__ W1, const float* __restrict__ Wc1) {
    if (blockIdx.x == 0) {
        if (threadIdx.x < Cc) g_cnt[threadIdx.x] = 0;
        if (threadIdx.x == Cc) g_unr_cnt = 0;
    }
    int t = blockIdx.x * 256 + threadIdx.x;       // 9*16*32*32 = 147456 total
    int lane = t & 31;
    int n8   = (t >> 5) & 31;
    int kc   = (t >> 10) & 15;
    int mat  = t >> 14;
    const float* W = (mat == 0) ? W1 : (Wc1 + (size_t)(mat - 1) * 65536);
    int k = kc * 16 + (lane & 3) * 2;
    int n = n8 * 8 + (lane >> 2);
    float v00 = W[(size_t)k * 256 + n];
    float v01 = W[(size_t)(k + 1) * 256 + n];
    float v10 = W[(size_t)(k + 8) * 256 + n];
    float v11 = W[(size_t)(k + 9) * 256 + n];
    float h00, l00, h01, l01, h10, l10, h11, l11;
    h_split(v00, h00, l00);
    h_split(v01, h01, l01);
    h_split(v10, h10, l10);
    h_split(v11, h11, l11);
    uint4 f;
    f.x = pack_h2(h00, h01);
    f.y = pack_h2(h10, h11);
    f.z = pack_h2(l00, l01);
    f.w = pack_h2(l10, l11);
    g_wfrag[t] = f;
}

// smem layout (bytes): A stages 2 x (hi 4KB | lo 4KB) = 16KB, B stages 2 x 8KB
#define SM_A(s)   ((s) * 8192)
#define SM_ALO_OFF 4096
#define SM_B(s)   (16384 + (s) * 8192)
#define SM_BYTES_MAIN 32768
#define SMEM_BYTES (SM_BYTES_MAIN + 1536)

__device__ __forceinline__ int a_off(int r, int c) {
    return r * 32 + ((c ^ ((r >> 2) & 1)) << 4);
}

// ---------------------------------------------------------------------------
// fp16 2-split (3-term) GEMM: [128 rows, nBase..+128) = relu(A@W + bias)
// Root: writes g_h only + head partials (W2) -> g_plog.
// Gather: writes routed rows of Out + expert-head partials (Wc2) -> g_plog.
// ---------------------------------------------------------------------------
template<bool GATHER>
__global__ __launch_bounds__(256, 2)
void gemm_mma(const float* __restrict__ Ain,
              const float* __restrict__ ball,
              const float* __restrict__ Whead,
              float* __restrict__ Out)
{
    extern __shared__ char sm[];
    int* ridx = (int*)(sm + SM_BYTES_MAIN);
    float* W2s = (float*)(sm);   // reused after mainloop

    const int tid  = threadIdx.x;
    const int wid  = tid >> 5;
    const int lane = tid & 31;
    const int mBase = blockIdx.y * 128;
    const int nBase = blockIdx.x * 128;

    const float* A;
    const float* bias;
    const float* whead_src;
    int mat;
    if (GATHER) {
        const int c   = blockIdx.z;
        const int cnt = g_cnt[c];
        if (mBase >= cnt) return;
        A    = g_h;
        bias = ball + c * 256;
        mat  = 1 + c;
        whead_src = Whead + (size_t)c * 2048 + (size_t)nBase * 8;
        if (tid < 128) {
            int gi = mBase + tid;
            ridx[tid] = (gi < cnt) ? g_idx[c * Bn + gi] : -1;
        }
        __syncthreads();
    } else {
        A    = Ain;
        bias = ball;
        mat  = 0;
        whead_src = Whead + (size_t)nBase * 8;
    }

    const int ar = tid >> 1;
    const int ah = tid & 1;
    int grow = GATHER ? ridx[ar] : (mBase + ar);
    const bool aok = (!GATHER) || (grow >= 0);
    const float* ap = A + (size_t)(aok ? grow : 0) * 256 + ah * 8;
    const int aoff = a_off(ar, ah);

    const int bx16 = blockIdx.x * 16;
    const uint32_t smb = smem_u32(sm);

    const int warp_m = wid & 3;
    const int warp_n = wid >> 2;

    int lm_off[2];
    {
        int mt = lane >> 3;
        int kb2 = mt >> 1;
        #pragma unroll
        for (int i = 0; i < 2; i++) {
            int row = warp_m * 32 + i * 16 + (mt & 1) * 8 + (lane & 7);
            lm_off[i] = a_off(row, kb2);
        }
    }

    float acc[2][8][4];
    #pragma unroll
    for (int i = 0; i < 2; i++)
        #pragma unroll
        for (int j = 0; j < 8; j++)
            #pragma unroll
            for (int t = 0; t < 4; t++) acc[i][j][t] = 0.f;

    auto stageA = [&](int buf, const float4* v) {
        uint4 hi4, lo4;
        float h0, l0, h1, l1;
        h_split(v[0].x, h0, l0); h_split(v[0].y, h1, l1);
        hi4.x = pack_h2(h0, h1); lo4.x = pack_h2(l0, l1);
        h_split(v[0].z, h0, l0); h_split(v[0].w, h1, l1);
        hi4.y = pack_h2(h0, h1); lo4.y = pack_h2(l0, l1);
        h_split(v[1].x, h0, l0); h_split(v[1].y, h1, l1);
        hi4.z = pack_h2(h0, h1); lo4.z = pack_h2(l0, l1);
        h_split(v[1].z, h0, l0); h_split(v[1].w, h1, l1);
        hi4.w = pack_h2(h0, h1); lo4.w = pack_h2(l0, l1);
        *(uint4*)(sm + SM_A(buf) + aoff)              = hi4;
        *(uint4*)(sm + SM_A(buf) + SM_ALO_OFF + aoff) = lo4;
    };
    auto stageB = [&](int buf, int kb) {
        uint32_t dbase = smb + SM_B(buf);
        #pragma unroll
        for (int i = 0; i < 2; i++) {
            int t   = tid + i * 256;
            int ln  = t & 31;
            int n8l = t >> 5;
            const uint4* src = g_wfrag +
                ((size_t)(mat * 16 + kb) * 32 + bx16 + n8l) * 32 + ln;
            CP_ASYNC16(dbase + (uint32_t)t * 16, (const void*)src);
        }
        CP_COMMIT();
    };

    {
        float4 av[2];
        av[0] = aok ? *(const float4*)(ap)     : make_float4(0.f, 0.f, 0.f, 0.f);
        av[1] = aok ? *(const float4*)(ap + 4) : make_float4(0.f, 0.f, 0.f, 0.f);
        stageA(0, av);
        stageB(0, 0);
        CP_WAIT0();
        __syncthreads();
    }

    for (int kb = 0; kb < 16; kb++) {
        const int p = kb & 1;
        float4 nv[2];
        if (kb < 15) {
            stageB(p ^ 1, kb + 1);
            nv[0] = aok ? *(const float4*)(ap + (kb + 1) * 16)     : make_float4(0.f, 0.f, 0.f, 0.f);
            nv[1] = aok ? *(const float4*)(ap + (kb + 1) * 16 + 4) : make_float4(0.f, 0.f, 0.f, 0.f);
        }

        uint32_t ahf[2][4], alf[2][4];
        #pragma unroll
        for (int i = 0; i < 2; i++) {
            ldmatrix_x4(ahf[i], smb + SM_A(p) + lm_off[i]);
            ldmatrix_x4(alf[i], smb + SM_A(p) + SM_ALO_OFF + lm_off[i]);
        }

        const char* BST = sm + SM_B(p);
        #pragma unroll
        for (int j = 0; j < 8; j++) {
            uint4 bf = *(const uint4*)(BST + (((warp_n * 8 + j) * 32 + lane) << 4));
            #pragma unroll
            for (int i = 0; i < 2; i++) {
                mma_f16(acc[i][j], ahf[i], bf.x, bf.y);
                mma_f16(acc[i][j], ahf[i], bf.z, bf.w);
                mma_f16(acc[i][j], alf[i], bf.x, bf.y);
            }
        }

        if (kb < 15) {
            stageA(p ^ 1, nv);
            CP_WAIT0();
            __syncthreads();
        }
    }

    // ---- head-weight slice (128 cols x 8 cls) into smem (dead after mainloop)
    __syncthreads();
    if (tid < 256) {
        *(float4*)(W2s + tid * 4) = *(const float4*)(whead_src + tid * 4);
    }
    __syncthreads();

    // ---- epilogue: bias + relu, store; accumulate partial head logits
    const int g  = lane >> 2;
    const int tg = lane & 3;
    float plg[2][2][8];
    #pragma unroll
    for (int i = 0; i < 2; i++)
        #pragma unroll
        for (int h = 0; h < 2; h++)
            #pragma unroll
            for (int cls = 0; cls < 8; cls++) plg[i][h][cls] = 0.f;

    #pragma unroll
    for (int i = 0; i < 2; i++) {
        int rl0 = warp_m * 32 + i * 16 + g;
        int rl1 = rl0 + 8;
        int r0, r1;
        if (GATHER) { r0 = ridx[rl0]; r1 = ridx[rl1]; }
        else        { r0 = mBase + rl0; r1 = mBase + rl1; }
        #pragma unroll
        for (int j = 0; j < 8; j++) {
            int colL = warp_n * 64 + j * 8 + tg * 2;
            int col  = nBase + colL;
            float bv0 = __ldg(bias + col);
            float bv1 = __ldg(bias + col + 1);
            float2 v0 = make_float2(fmaxf(acc[i][j][0] + bv0, 0.f),
                                    fmaxf(acc[i][j][1] + bv1, 0.f));
            float2 v1 = make_float2(fmaxf(acc[i][j][2] + bv0, 0.f),
                                    fmaxf(acc[i][j][3] + bv1, 0.f));
            const float* w0 = W2s + colL * 8;
            const float* w1 = w0 + 8;
            if (!GATHER) {
                *(float2*)(g_h + (size_t)r0 * 256 + col) = v0;
                *(float2*)(g_h + (size_t)r1 * 256 + col) = v1;
                #pragma unroll
                for (int cls = 0; cls < 8; cls++) {
                    plg[i][0][cls] += v0.x * w0[cls] + v0.y * w1[cls];
                    plg[i][1][cls] += v1.x * w0[cls] + v1.y * w1[cls];
                }
            } else {
                if (r0 >= 0) {
                    *(float2*)(Out + (size_t)r0 * 256 + col) = v0;
                    #pragma unroll
                    for (int cls = 0; cls < 8; cls++)
                        plg[i][0][cls] += v0.x * w0[cls] + v0.y * w1[cls];
                }
                if (r1 >= 0) {
                    *(float2*)(Out + (size_t)r1 * 256 + col) = v1;
                    #pragma unroll
                    for (int cls = 0; cls < 8; cls++)
                        plg[i][1][cls] += v1.x * w0[cls] + v1.y * w1[cls];
                }
            }
        }
    }

    // reduce plg over the 4 tg-lanes, store partials (layout [s][q][8])
    #pragma unroll
    for (int i = 0; i < 2; i++)
        #pragma unroll
        for (int h = 0; h < 2; h++)
            #pragma unroll
            for (int cls = 0; cls < 8; cls++) {
                float v = plg[i][h][cls];
                v += __shfl_xor_sync(0xffffffffu, v, 1);
                v += __shfl_xor_sync(0xffffffffu, v, 2);
                plg[i][h][cls] = v;
            }
    if (tg == 0) {
        int q = blockIdx.x * 2 + warp_n;
        #pragma unroll
        for (int i = 0; i < 2; i++) {
            int rl0 = warp_m * 32 + i * 16 + g;
            int r0, r1;
            if (GATHER) { r0 = ridx[rl0]; r1 = ridx[rl0 + 8]; }
            else        { r0 = mBase + rl0; r1 = r0 + 8; }
            if (!GATHER || r0 >= 0) {
                float* p0 = g_plog + (size_t)r0 * 32 + q * 8;
                *(float4*)(p0)     = *(float4*)&plg[i][0][0];
                *(float4*)(p0 + 4) = *(float4*)&plg[i][0][4];
            }
            if (!GATHER || r1 >= 0) {
                float* p1 = g_plog + (size_t)r1 * 32 + q * 8;
                *(float4*)(p1)     = *(float4*)&plg[i][1][0];
                *(float4*)(p1 + 4) = *(float4*)&plg[i][1][4];
            }
        }
    }
}

// ---------------------------------------------------------------------------
// Routing: 2 consecutive samples per thread (ILP: 16 loads in flight),
// softmax + tau-mask argmax each, warp-aggregated compaction.
// ---------------------------------------------------------------------------
__global__ __launch_bounds__(256)
void route_kernel(const float* __restrict__ b2, const float* __restrict__ tau,
                  float* __restrict__ outLogits, float* __restrict__ outDepth)
{
    const int t    = blockIdx.x * 256 + threadIdx.x;
    const int s0   = t * 2;
    const int lane = threadIdx.x & 31;

    // issue all 16 loads before consuming (MLP 16)
    float4 p[2][8];
    #pragma unroll
    for (int u = 0; u < 2; u++) {
        const float4* pp = (const float4*)(g_plog + (size_t)(s0 + u) * 32);
        #pragma unroll
        for (int q = 0; q < 8; q++) p[u][q] = pp[q];
    }

    float b2v[8], tauv[8];
    #pragma unroll
    for (int j = 0; j < 8; j++) { b2v[j] = __ldg(b2 + j); tauv[j] = __ldg(tau + j); }

    int best[2];
    #pragma unroll
    for (int u = 0; u < 2; u++) {
        float lg[8];
        #pragma unroll
        for (int j = 0; j < 8; j++) lg[j] = b2v[j];
        #pragma unroll
        for (int q = 0; q < 4; q++) {
            float4 q0 = p[u][q * 2];
            float4 q1 = p[u][q * 2 + 1];
            lg[0] += q0.x; lg[1] += q0.y; lg[2] += q0.z; lg[3] += q0.w;
            lg[4] += q1.x; lg[5] += q1.y; lg[6] += q1.z; lg[7] += q1.w;
        }
        float mx = -1e30f;
        #pragma unroll
        for (int j = 0; j < 8; j++) mx = fmaxf(mx, lg[j]);
        float e[8], ss = 0.f;
        #pragma unroll
        for (int j = 0; j < 8; j++) { e[j] = expf(lg[j] - mx); ss += e[j]; }
        float inv = 1.0f / ss;
        int b = -1; float bp = -1.f;
        #pragma unroll
        for (int j = 0; j < 8; j++) {
            float pj = e[j] * inv;
            if (pj >= tauv[j] && pj > bp) { bp = pj; b = j; }
        }
        best[u] = b;
        float* lo = outLogits + (size_t)(s0 + u) * 8;
        *(float4*)(lo)     = make_float4(lg[0], lg[1], lg[2], lg[3]);
        *(float4*)(lo + 4) = make_float4(lg[4], lg[5], lg[6], lg[7]);
    }
    *(float2*)(outDepth + s0) = make_float2(best[0] >= 0 ? 1.0f : 0.0f,
                                            best[1] >= 0 ? 1.0f : 0.0f);

    // warp-aggregated compaction, 2 rounds
    #pragma unroll
    for (int u = 0; u < 2; u++) {
        int s = s0 + u;
        int b = best[u];
        #pragma unroll
        for (int c = 0; c < 8; c++) {
            unsigned mask = __ballot_sync(0xffffffffu, b == c);
            if (b == c) {
                int leader = __ffs(mask) - 1;
                int base = 0;
                if (lane == leader) base = atomicAdd(&g_cnt[c], __popc(mask));
                base = __shfl_sync(mask, base, leader);
                int pos = base + __popc(mask & ((1u << lane) - 1u));
                g_idx[c * Bn + pos] = s;
            }
        }
        bool unrouted = (b < 0);
        unsigned mask = __ballot_sync(0xffffffffu, unrouted);
        if (unrouted) {
            int leader = __ffs(mask) - 1;
            int base = 0;
            if (lane == leader) base = atomicAdd(&g_unr_cnt, __popc(mask));
            base = __shfl_sync(mask, base, leader);
            int pos = base + __popc(mask & ((1u << lane) - 1u));
            g_unr[pos] = s;
        }
    }
}

// ---------------------------------------------------------------------------
// Copy unrouted rows g_h -> outH (one warp per row, grid-strided).
// ---------------------------------------------------------------------------
__global__ __launch_bounds__(256)
void copy_unrouted(float* __restrict__ outH)
{
    const int lane = threadIdx.x & 31;
    const int wid  = threadIdx.x >> 5;
    const int cnt  = g_unr_cnt;
    for (int r = blockIdx.x * 8 + wid; r < cnt; r += gridDim.x * 8) {
        int s = g_unr[r];
        const float4* src = (const float4*)(g_h + (size_t)s * 256);
        float4*       dst = (float4*)(outH + (size_t)s * 256);
        dst[lane]      = src[lane];
        dst[lane + 32] = src[lane + 32];
    }
}

// ---------------------------------------------------------------------------
// Expert combine: routed samples get logits = sum of 4 partials + bc2[c].
// ---------------------------------------------------------------------------
__global__ __launch_bounds__(256)
void expert_combine(const float* __restrict__ bc2, float* __restrict__ outLogits)
{
    const int c   = blockIdx.y;
    const int cnt = g_cnt[c];
    const int i   = blockIdx.x * 256 + threadIdx.x;
    if (i >= cnt) return;
    const int s = g_idx[c * Bn + i];
    const float4* pp = (const float4*)(g_plog + (size_t)s * 32);
    float lg[8];
    #pragma unroll
    for (int j = 0; j < 8; j++) lg[j] = __ldg(bc2 + c * 8 + j);
    #pragma unroll
    for (int q = 0; q < 4; q++) {
        float4 p0 = pp[q * 2];
        float4 p1 = pp[q * 2 + 1];
        lg[0] += p0.x; lg[1] += p0.y; lg[2] += p0.z; lg[3] += p0.w;
        lg[4] += p1.x; lg[5] += p1.y; lg[6] += p1.z; lg[7] += p1.w;
    }
    float* lo = outLogits + (size_t)s * 8;
    *(float4*)(lo)     = make_float4(lg[0], lg[1], lg[2], lg[3]);
    *(float4*)(lo + 4) = make_float4(lg[4], lg[5], lg[6], lg[7]);
}

// ---------------------------------------------------------------------------
extern "C" void kernel_launch(void* const* d_in, const int* in_sizes, int n_in,
                              void* d_out, int out_size)
{
    const float* x   = (const float*)d_in[0];
    const float* W1  = (const float*)d_in[1];
    const float* b1  = (const float*)d_in[2];
    const float* W2  = (const float*)d_in[3];
    const float* b2  = (const float*)d_in[4];
    const float* Wc1 = (const float*)d_in[5];
    const float* bc1 = (const float*)d_in[6];
    const float* Wc2 = (const float*)d_in[7];
    const float* bc2 = (const float*)d_in[8];
    const float* tau = (const float*)d_in[9];

    float* out       = (float*)d_out;
    float* outLogits = out;
    float* outH      = out + (size_t)Bn * Cc;
    float* outDepth  = out + (size_t)Bn * (Cc + Hh);

    static bool attr_done = false;
    if (!attr_done) {
        cudaFuncSetAttribute(gemm_mma<false>, cudaFuncAttributeMaxDynamicSharedMemorySize, SMEM_BYTES);
        cudaFuncSetAttribute(gemm_mma<true>,  cudaFuncAttributeMaxDynamicSharedMemorySize, SMEM_BYTES);
        attr_done = true;
    }

    // One-time W fragment split (W1 + 8 experts); block 0 zeroes counters
    split_wfrag<<<(9 * 16 * 32 * 32) / 256, 256>>>(W1, Wc1);

    // Root: h = relu(x @ W1 + b1) -> g_h, fused head partials -> g_plog
    gemm_mma<false><<<dim3(2, Bn / 128, 1), 256, SMEM_BYTES>>>(x, b1, W2, outH);

    // Routing from partial logits (2 samples/thread ILP)
    route_kernel<<<Bn / 512, 256>>>(b2, tau, outLogits, outDepth);

    // Unrouted rows: outH = h
    copy_unrouted<<<1024, 256>>>(outH);

    // Expert dense: gather from g_h, write routed rows of outH,
    // fused expert-head partials -> g_plog (routed rows only)
    gemm_mma<true><<<dim3(2, Bn / 128, Cc), 256, SMEM_BYTES>>>(nullptr, bc1, Wc2, outH);

    // Expert head combine for routed rows
    expert_combine<<<dim3(Bn / 256, Cc), 256>>>(bc2, outLogits);
}